// round 1
// baseline (speedup 1.0000x reference)
#include <cuda_runtime.h>
#include <math.h>

#define B_   128
#define T_   64
#define E_   512
#define H_   512
#define V_   10000
#define FIN_ 2048

// ---------------- scratch (device globals; no allocation) ----------------
__device__ float g_f[B_ * E_];          // pre-BN fc output
__device__ float g_feats[B_ * E_];      // BN output
__device__ float g_h[B_ * H_];          // hidden state
__device__ float g_xh[B_ * (E_ + H_)];  // concat(x, h)
__device__ float g_xa[B_ * (E_ + H_)];  // concat(x, applied)
__device__ float g_attn[B_ * H_];       // attn logits
__device__ float g_inp[B_ * H_];        // comb output
__device__ float g_gx[B_ * 3 * H_];
__device__ float g_gh[B_ * 3 * H_];
__device__ float g_hs[T_ * B_ * H_];    // time-major hidden states

// ---------------- generic SGEMM: C[M,N] = A[M,K] @ W[N,K]^T + bias ----------------
// BM=BN=64, BK=16, 256 threads, 4x4 per thread. K must be a multiple of 16.
#define BM 64
#define BN 64
#define BK 16

__global__ __launch_bounds__(256) void sgemm_tn(
    const float* __restrict__ A, const float* __restrict__ W,
    const float* __restrict__ bias, float* __restrict__ C,
    int M, int N, int K)
{
    __shared__ float As[BK][BM + 1];
    __shared__ float Ws[BK][BN + 1];

    const int tid = threadIdx.x;
    const int tx = tid & 15;        // N-dir
    const int ty = tid >> 4;        // M-dir
    const int rowBase = blockIdx.y * BM;
    const int colBase = blockIdx.x * BN;

    float acc[4][4] = {};

    for (int k0 = 0; k0 < K; k0 += BK) {
        #pragma unroll
        for (int i = 0; i < 4; i++) {
            int lin = tid + i * 256;          // 0..1023
            int r = lin >> 4;                 // 0..63
            int c = lin & 15;                 // 0..15
            int ar = rowBase + r;
            As[c][r] = (ar < M) ? A[(size_t)ar * K + k0 + c] : 0.f;
            int wr = colBase + r;
            Ws[c][r] = (wr < N) ? W[(size_t)wr * K + k0 + c] : 0.f;
        }
        __syncthreads();
        #pragma unroll
        for (int kk = 0; kk < BK; kk++) {
            float a[4], w[4];
            #pragma unroll
            for (int i = 0; i < 4; i++) a[i] = As[kk][ty * 4 + i];
            #pragma unroll
            for (int j = 0; j < 4; j++) w[j] = Ws[kk][tx * 4 + j];
            #pragma unroll
            for (int i = 0; i < 4; i++)
                #pragma unroll
                for (int j = 0; j < 4; j++)
                    acc[i][j] += a[i] * w[j];
        }
        __syncthreads();
    }

    #pragma unroll
    for (int i = 0; i < 4; i++) {
        int r = rowBase + ty * 4 + i;
        if (r >= M) continue;
        #pragma unroll
        for (int j = 0; j < 4; j++) {
            int c = colBase + tx * 4 + j;
            if (c < N) C[(size_t)r * N + c] = acc[i][j] + (bias ? bias[c] : 0.f);
        }
    }
}

// ---------------- BatchNorm1d (training mode, biased var, eps=1e-5) ----------------
// one block per feature column e; 128 threads = batch
__global__ void bn_kernel(const float* __restrict__ gamma, const float* __restrict__ beta)
{
    int e = blockIdx.x;
    int b = threadIdx.x;
    float v = g_f[b * E_ + e];
    __shared__ float red[B_];
    __shared__ float mu_s, var_s;

    red[b] = v;
    __syncthreads();
    for (int s = B_ / 2; s > 0; s >>= 1) {
        if (b < s) red[b] += red[b + s];
        __syncthreads();
    }
    if (b == 0) mu_s = red[0] * (1.0f / B_);
    __syncthreads();
    float d = v - mu_s;
    red[b] = d * d;
    __syncthreads();
    for (int s = B_ / 2; s > 0; s >>= 1) {
        if (b < s) red[b] += red[b + s];
        __syncthreads();
    }
    if (b == 0) var_s = red[0] * (1.0f / B_);
    __syncthreads();
    g_feats[b * E_ + e] = gamma[e] * d * rsqrtf(var_s + 1e-5f) + beta[e];
}

// ---------------- build concat(x_t, h) ----------------
__global__ void prep_kernel(const float* __restrict__ embed_W,
                            const int* __restrict__ captions, int t)
{
    int idx = blockIdx.x * blockDim.x + threadIdx.x;   // B*(E+H)
    int b = idx >> 10;
    int k = idx & 1023;
    float v;
    if (k < E_) {
        if (t == 0) v = g_feats[b * E_ + k];
        else        v = embed_W[(size_t)captions[b * T_ + (t - 1)] * E_ + k];
    } else {
        v = g_h[b * H_ + (k - E_)];
    }
    g_xh[idx] = v;
}

// ---------------- row softmax over attn logits + build concat(x, feats*aw) ----------------
__global__ void softmax_apply_kernel()
{
    int b = blockIdx.x;
    int j = threadIdx.x;      // 512 threads
    __shared__ float red[H_];
    __shared__ float mx_s, sum_s;

    float v = g_attn[b * H_ + j];
    red[j] = v;
    __syncthreads();
    for (int s = H_ / 2; s > 0; s >>= 1) {
        if (j < s) red[j] = fmaxf(red[j], red[j + s]);
        __syncthreads();
    }
    if (j == 0) mx_s = red[0];
    __syncthreads();
    float e = expf(v - mx_s);
    red[j] = e;
    __syncthreads();
    for (int s = H_ / 2; s > 0; s >>= 1) {
        if (j < s) red[j] += red[j + s];
        __syncthreads();
    }
    if (j == 0) sum_s = red[0];
    __syncthreads();
    float aw = e / sum_s;

    g_xa[b * 1024 + j]       = g_xh[b * 1024 + j];          // x part
    g_xa[b * 1024 + E_ + j]  = g_feats[b * E_ + j] * aw;    // applied part
}

// ---------------- GRU gates ----------------
__device__ __forceinline__ float sigmoidf_(float x) { return 1.0f / (1.0f + expf(-x)); }

__global__ void gate_kernel(int t)
{
    int idx = blockIdx.x * blockDim.x + threadIdx.x;   // B*H
    int b = idx >> 9;
    int j = idx & 511;
    const float* gx = g_gx + (size_t)b * 3 * H_;
    const float* gh = g_gh + (size_t)b * 3 * H_;
    float r = sigmoidf_(gx[j]          + gh[j]);
    float z = sigmoidf_(gx[H_ + j]     + gh[H_ + j]);
    float n = tanhf    (gx[2 * H_ + j] + r * gh[2 * H_ + j]);
    float hprev = g_h[idx];
    float h = (1.0f - z) * n + z * hprev;
    g_h[idx] = h;
    g_hs[(size_t)t * B_ * H_ + idx] = h;
}

// ---------------- log_softmax in place over rows of V ----------------
__global__ void logsoftmax_kernel(float* __restrict__ out)
{
    extern __shared__ float row[];      // V_ floats (40000 B)
    __shared__ float red[256];
    __shared__ float mx_s, lse_s;
    int r = blockIdx.x;
    int tid = threadIdx.x;
    float* p = out + (size_t)r * V_;

    float mx = -3.4e38f;
    for (int i = tid; i < V_; i += 256) {
        float v = p[i];
        row[i] = v;
        mx = fmaxf(mx, v);
    }
    red[tid] = mx;
    __syncthreads();
    for (int s = 128; s > 0; s >>= 1) {
        if (tid < s) red[tid] = fmaxf(red[tid], red[tid + s]);
        __syncthreads();
    }
    if (tid == 0) mx_s = red[0];
    __syncthreads();

    float sum = 0.f;
    for (int i = tid; i < V_; i += 256) sum += expf(row[i] - mx_s);
    red[tid] = sum;
    __syncthreads();
    for (int s = 128; s > 0; s >>= 1) {
        if (tid < s) red[tid] += red[tid + s];
        __syncthreads();
    }
    if (tid == 0) lse_s = mx_s + logf(red[0]);
    __syncthreads();

    for (int i = tid; i < V_; i += 256) p[i] = row[i] - lse_s;
}

// ---------------- transpose hs [T,B,H] -> hiddens [B,T,H] ----------------
__global__ void transpose_h_kernel(float* __restrict__ out2)
{
    int idx = blockIdx.x * blockDim.x + threadIdx.x;    // T*B*H
    int j = idx & 511;
    int b = (idx >> 9) & 127;
    int t = idx >> 16;
    out2[((size_t)b * T_ + t) * H_ + j] = g_hs[idx];
}

// ---------------- host launch ----------------
extern "C" void kernel_launch(void* const* d_in, const int* in_sizes, int n_in,
                              void* d_out, int out_size)
{
    const float* features = (const float*)d_in[0];
    const int*   captions = (const int*)d_in[1];
    const float* h0       = (const float*)d_in[2];
    // d_in[3] = lengths (constant T=64), unused
    const float* embed_W  = (const float*)d_in[4];
    const float* fc_W     = (const float*)d_in[5];
    const float* fc_b     = (const float*)d_in[6];
    const float* bn_gamma = (const float*)d_in[7];
    const float* bn_beta  = (const float*)d_in[8];
    const float* attn_W   = (const float*)d_in[9];
    const float* attn_b   = (const float*)d_in[10];
    const float* comb_W   = (const float*)d_in[11];
    const float* comb_b   = (const float*)d_in[12];
    const float* gru_Wih  = (const float*)d_in[13];
    const float* gru_Whh  = (const float*)d_in[14];
    const float* gru_bih  = (const float*)d_in[15];
    const float* gru_bhh  = (const float*)d_in[16];
    const float* out_W    = (const float*)d_in[17];
    const float* out_b    = (const float*)d_in[18];
    float* out = (float*)d_out;

    float *p_f, *p_h, *p_xh, *p_xa, *p_attn, *p_inp, *p_gx, *p_gh, *p_hs;
    cudaGetSymbolAddress((void**)&p_f,    g_f);
    cudaGetSymbolAddress((void**)&p_h,    g_h);
    cudaGetSymbolAddress((void**)&p_xh,   g_xh);
    cudaGetSymbolAddress((void**)&p_xa,   g_xa);
    cudaGetSymbolAddress((void**)&p_attn, g_attn);
    cudaGetSymbolAddress((void**)&p_inp,  g_inp);
    cudaGetSymbolAddress((void**)&p_gx,   g_gx);
    cudaGetSymbolAddress((void**)&p_gh,   g_gh);
    cudaGetSymbolAddress((void**)&p_hs,   g_hs);

    cudaMemcpyAsync(p_h, h0, (size_t)B_ * H_ * sizeof(float), cudaMemcpyDeviceToDevice);

    dim3 blk(256);

    // fc + batchnorm
    sgemm_tn<<<dim3(E_ / 64, B_ / 64), blk>>>(features, fc_W, fc_b, p_f, B_, E_, FIN_);
    bn_kernel<<<E_, B_>>>(bn_gamma, bn_beta);

    // recurrence
    for (int t = 0; t < T_; t++) {
        prep_kernel<<<(B_ * (E_ + H_)) / 256, 256>>>(embed_W, captions, t);
        sgemm_tn<<<dim3(H_ / 64, B_ / 64), blk>>>(p_xh, attn_W, attn_b, p_attn, B_, H_, E_ + H_);
        softmax_apply_kernel<<<B_, H_>>>();
        sgemm_tn<<<dim3(H_ / 64, B_ / 64), blk>>>(p_xa, comb_W, comb_b, p_inp, B_, H_, E_ + H_);
        sgemm_tn<<<dim3(3 * H_ / 64, B_ / 64), blk>>>(p_inp, gru_Wih, gru_bih, p_gx, B_, 3 * H_, H_);
        sgemm_tn<<<dim3(3 * H_ / 64, B_ / 64), blk>>>(p_h,   gru_Whh, gru_bhh, p_gh, B_, 3 * H_, H_);
        gate_kernel<<<(B_ * H_) / 256, 256>>>(t);
    }

    // vocab projection + log_softmax (in place on d_out)
    sgemm_tn<<<dim3((V_ + 63) / 64, (T_ * B_) / 64), blk>>>(p_hs, out_W, out_b, out,
                                                            T_ * B_, V_, H_);
    logsoftmax_kernel<<<T_ * B_, 256, V_ * sizeof(float)>>>(out);

    // hiddens output after log-probs
    transpose_h_kernel<<<(T_ * B_ * H_) / 256, 256>>>(out + (size_t)T_ * B_ * V_);
}

// round 4
// speedup vs baseline: 1.6611x; 1.6611x over previous
#include <cuda_runtime.h>
#include <math.h>

#define B_   128
#define T_   64
#define E_   512
#define H_   512
#define V_   10000
#define FIN_ 2048

// ---------------- scratch (device globals; no allocation) ----------------
__device__ float g_f[B_ * E_];              // pre-BN fc output
__device__ float g_feats[B_ * E_];          // BN output
__device__ float g_h[B_ * H_];              // hidden state
__device__ float g_X[T_ * B_ * E_];         // x_t for all steps (time-major)
__device__ float g_AX[T_ * B_ * H_];        // X @ attn_Wx^T + attn_b
__device__ float g_CX[T_ * B_ * H_];        // X @ comb_Wx^T + comb_b
__device__ float g_Whcat[2048 * H_];        // [attn_Wh ; gru_Whh] rows
__device__ float g_hproj[B_ * 2048];        // h @ Whcat^T
__device__ float g_applied[B_ * E_];        // feats * aw
__device__ float g_inp[B_ * H_];            // comb output
__device__ float g_gx[B_ * 3 * H_];
__device__ float g_hs[T_ * B_ * H_];        // time-major hidden states

// ---------------- generic SGEMM: C[M,N] = A[M,K] @ W[N,K]^T (+bias)(+D) ----
// BM=BN=64, BK=16, 256 threads, 4x4 per thread. K multiple of 16.
#define BM 64
#define BN 64
#define BK 16

__global__ __launch_bounds__(256) void sgemm2(
    const float* __restrict__ A, int lda,
    const float* __restrict__ W, int ldw,
    const float* __restrict__ bias,
    const float* __restrict__ D, int ldd,
    float* __restrict__ C, int ldc,
    int M, int N, int K)
{
    __shared__ float As[BK][BM + 1];
    __shared__ float Ws[BK][BN + 1];

    const int tid = threadIdx.x;
    const int tx = tid & 15;        // N-dir
    const int ty = tid >> 4;        // M-dir
    const int rowBase = blockIdx.y * BM;
    const int colBase = blockIdx.x * BN;

    float acc[4][4] = {};

    for (int k0 = 0; k0 < K; k0 += BK) {
        #pragma unroll
        for (int i = 0; i < 4; i++) {
            int lin = tid + i * 256;          // 0..1023
            int r = lin >> 4;                 // 0..63
            int c = lin & 15;                 // 0..15
            int ar = rowBase + r;
            As[c][r] = (ar < M) ? A[(size_t)ar * lda + k0 + c] : 0.f;
            int wr = colBase + r;
            Ws[c][r] = (wr < N) ? W[(size_t)wr * ldw + k0 + c] : 0.f;
        }
        __syncthreads();
        #pragma unroll
        for (int kk = 0; kk < BK; kk++) {
            float a[4], w[4];
            #pragma unroll
            for (int i = 0; i < 4; i++) a[i] = As[kk][ty * 4 + i];
            #pragma unroll
            for (int j = 0; j < 4; j++) w[j] = Ws[kk][tx * 4 + j];
            #pragma unroll
            for (int i = 0; i < 4; i++)
                #pragma unroll
                for (int j = 0; j < 4; j++)
                    acc[i][j] += a[i] * w[j];
        }
        __syncthreads();
    }

    #pragma unroll
    for (int i = 0; i < 4; i++) {
        int r = rowBase + ty * 4 + i;
        if (r >= M) continue;
        #pragma unroll
        for (int j = 0; j < 4; j++) {
            int c = colBase + tx * 4 + j;
            if (c < N) {
                float v = acc[i][j];
                if (bias) v += bias[c];
                if (D)    v += D[(size_t)r * ldd + c];
                C[(size_t)r * ldc + c] = v;
            }
        }
    }
}

// ---------------- BatchNorm1d (training mode, biased var, eps=1e-5) --------
__global__ void bn_kernel(const float* __restrict__ gamma, const float* __restrict__ beta)
{
    int e = blockIdx.x;
    int b = threadIdx.x;
    float v = g_f[b * E_ + e];
    __shared__ float red[B_];
    __shared__ float mu_s, var_s;

    red[b] = v;
    __syncthreads();
    for (int s = B_ / 2; s > 0; s >>= 1) {
        if (b < s) red[b] += red[b + s];
        __syncthreads();
    }
    if (b == 0) mu_s = red[0] * (1.0f / B_);
    __syncthreads();
    float d = v - mu_s;
    red[b] = d * d;
    __syncthreads();
    for (int s = B_ / 2; s > 0; s >>= 1) {
        if (b < s) red[b] += red[b + s];
        __syncthreads();
    }
    if (b == 0) var_s = red[0] * (1.0f / B_);
    __syncthreads();
    g_feats[b * E_ + e] = gamma[e] * d * rsqrtf(var_s + 1e-5f) + beta[e];
}

// ---------------- build X[t][b][e] for all steps --------------------------
__global__ void build_X_kernel(const float* __restrict__ embed_W,
                               const int* __restrict__ captions)
{
    int idx = blockIdx.x * blockDim.x + threadIdx.x;  // T*B*E
    int t = idx >> 16;              // B_*E_ = 65536
    int rem = idx & 65535;
    int b = rem >> 9;
    int e = rem & 511;
    float v;
    if (t == 0) v = g_feats[b * E_ + e];
    else        v = embed_W[(size_t)captions[b * T_ + (t - 1)] * E_ + e];
    g_X[idx] = v;
}

// ---------------- build concatenated h-weights [attn_Wh ; Whh] ------------
__global__ void build_Whcat_kernel(const float* __restrict__ attn_W,
                                   const float* __restrict__ gru_Whh)
{
    int idx = blockIdx.x * blockDim.x + threadIdx.x;  // 2048*512
    int n = idx >> 9;
    int k = idx & 511;
    float v;
    if (n < 512) v = attn_W[(size_t)n * 1024 + 512 + k];
    else         v = gru_Whh[(size_t)(n - 512) * 512 + k];
    g_Whcat[idx] = v;
}

// ---------------- softmax over (AX[t] + hproj[:, :512]) + apply -----------
__global__ void softmax_apply_kernel(int t)
{
    int b = blockIdx.x;
    int j = threadIdx.x;      // 512 threads
    __shared__ float red[H_];
    __shared__ float mx_s, sum_s;

    float v = g_AX[((size_t)t * B_ + b) * H_ + j] + g_hproj[b * 2048 + j];
    red[j] = v;
    __syncthreads();
    for (int s = H_ / 2; s > 0; s >>= 1) {
        if (j < s) red[j] = fmaxf(red[j], red[j + s]);
        __syncthreads();
    }
    if (j == 0) mx_s = red[0];
    __syncthreads();
    float e = expf(v - mx_s);
    red[j] = e;
    __syncthreads();
    for (int s = H_ / 2; s > 0; s >>= 1) {
        if (j < s) red[j] += red[j + s];
        __syncthreads();
    }
    if (j == 0) sum_s = red[0];
    __syncthreads();
    g_applied[b * E_ + j] = g_feats[b * E_ + j] * (e / sum_s);
}

// ---------------- GRU gates ----------------
__device__ __forceinline__ float sigmoidf_(float x) { return 1.0f / (1.0f + expf(-x)); }

__global__ void gate_kernel(int t, const float* __restrict__ bhh)
{
    int idx = blockIdx.x * blockDim.x + threadIdx.x;   // B*H
    int b = idx >> 9;
    int j = idx & 511;
    const float* gx = g_gx + (size_t)b * 3 * H_;
    const float* hp = g_hproj + (size_t)b * 2048 + 512;   // gh block
    float ghr = hp[j]          + bhh[j];
    float ghz = hp[H_ + j]     + bhh[H_ + j];
    float ghn = hp[2 * H_ + j] + bhh[2 * H_ + j];
    float r = sigmoidf_(gx[j]          + ghr);
    float z = sigmoidf_(gx[H_ + j]     + ghz);
    float n = tanhf    (gx[2 * H_ + j] + r * ghn);
    float hprev = g_h[idx];
    float h = (1.0f - z) * n + z * hprev;
    g_h[idx] = h;
    g_hs[(size_t)t * B_ * H_ + idx] = h;
}

// ---------------- log_softmax in place over rows of V ----------------
__global__ void logsoftmax_kernel(float* __restrict__ out)
{
    extern __shared__ float row[];      // V_ floats
    __shared__ float red[256];
    __shared__ float mx_s, lse_s;
    int r = blockIdx.x;
    int tid = threadIdx.x;
    float* p = out + (size_t)r * V_;

    float mx = -3.4e38f;
    for (int i = tid; i < V_; i += 256) {
        float v = p[i];
        row[i] = v;
        mx = fmaxf(mx, v);
    }
    red[tid] = mx;
    __syncthreads();
    for (int s = 128; s > 0; s >>= 1) {
        if (tid < s) red[tid] = fmaxf(red[tid], red[tid + s]);
        __syncthreads();
    }
    if (tid == 0) mx_s = red[0];
    __syncthreads();

    float sum = 0.f;
    for (int i = tid; i < V_; i += 256) sum += expf(row[i] - mx_s);
    red[tid] = sum;
    __syncthreads();
    for (int s = 128; s > 0; s >>= 1) {
        if (tid < s) red[tid] += red[tid + s];
        __syncthreads();
    }
    if (tid == 0) lse_s = mx_s + logf(red[0]);
    __syncthreads();

    for (int i = tid; i < V_; i += 256) p[i] = row[i] - lse_s;
}

// ---------------- transpose hs [T,B,H] -> hiddens [B,T,H] ----------------
__global__ void transpose_h_kernel(float* __restrict__ out2)
{
    int idx = blockIdx.x * blockDim.x + threadIdx.x;    // T*B*H
    int j = idx & 511;
    int b = (idx >> 9) & 127;
    int t = idx >> 16;
    out2[((size_t)b * T_ + t) * H_ + j] = g_hs[idx];
}

// ---------------- host launch ----------------
extern "C" void kernel_launch(void* const* d_in, const int* in_sizes, int n_in,
                              void* d_out, int out_size)
{
    const float* features = (const float*)d_in[0];
    const int*   captions = (const int*)d_in[1];
    const float* h0       = (const float*)d_in[2];
    const float* embed_W  = (const float*)d_in[4];
    const float* fc_W     = (const float*)d_in[5];
    const float* fc_b     = (const float*)d_in[6];
    const float* bn_gamma = (const float*)d_in[7];
    const float* bn_beta  = (const float*)d_in[8];
    const float* attn_W   = (const float*)d_in[9];
    const float* attn_b   = (const float*)d_in[10];
    const float* comb_W   = (const float*)d_in[11];
    const float* comb_b   = (const float*)d_in[12];
    const float* gru_Wih  = (const float*)d_in[13];
    const float* gru_Whh  = (const float*)d_in[14];
    const float* gru_bih  = (const float*)d_in[15];
    const float* gru_bhh  = (const float*)d_in[16];
    const float* out_W    = (const float*)d_in[17];
    const float* out_b    = (const float*)d_in[18];
    float* out = (float*)d_out;

    float *p_f, *p_h, *p_X, *p_AX, *p_CX, *p_Whcat, *p_hproj, *p_applied, *p_inp, *p_gx, *p_hs;
    cudaGetSymbolAddress((void**)&p_f,       g_f);
    cudaGetSymbolAddress((void**)&p_h,       g_h);
    cudaGetSymbolAddress((void**)&p_X,       g_X);
    cudaGetSymbolAddress((void**)&p_AX,      g_AX);
    cudaGetSymbolAddress((void**)&p_CX,      g_CX);
    cudaGetSymbolAddress((void**)&p_Whcat,   g_Whcat);
    cudaGetSymbolAddress((void**)&p_hproj,   g_hproj);
    cudaGetSymbolAddress((void**)&p_applied, g_applied);
    cudaGetSymbolAddress((void**)&p_inp,     g_inp);
    cudaGetSymbolAddress((void**)&p_gx,      g_gx);
    cudaGetSymbolAddress((void**)&p_hs,      g_hs);

    cudaMemcpyAsync(p_h, h0, (size_t)B_ * H_ * sizeof(float), cudaMemcpyDeviceToDevice);

    dim3 blk(256);

    // fc + batchnorm
    sgemm2<<<dim3(E_ / 64, B_ / 64), blk>>>(features, FIN_, fc_W, FIN_, fc_b,
                                            nullptr, 0, p_f, E_, B_, E_, FIN_);
    bn_kernel<<<E_, B_>>>(bn_gamma, bn_beta);

    // hoisted x-dependent work for all timesteps
    build_X_kernel<<<(T_ * B_ * E_) / 256, 256>>>(embed_W, captions);
    build_Whcat_kernel<<<(2048 * H_) / 256, 256>>>(attn_W, gru_Whh);
    // AX = X @ attn_W[:, :512]^T + attn_b
    sgemm2<<<dim3(H_ / 64, (T_ * B_) / 64), blk>>>(p_X, E_, attn_W, 1024, attn_b,
                                                   nullptr, 0, p_AX, H_,
                                                   T_ * B_, H_, E_);
    // CX = X @ comb_W[:, :512]^T + comb_b
    sgemm2<<<dim3(H_ / 64, (T_ * B_) / 64), blk>>>(p_X, E_, comb_W, 1024, comb_b,
                                                   nullptr, 0, p_CX, H_,
                                                   T_ * B_, H_, E_);

    // recurrence: 5 launches/step
    for (int t = 0; t < T_; t++) {
        // hproj = h @ [attn_Wh ; Whh]^T   [128 x 2048]
        sgemm2<<<dim3(2048 / 64, B_ / 64), blk>>>(p_h, H_, p_Whcat, H_, nullptr,
                                                  nullptr, 0, p_hproj, 2048,
                                                  B_, 2048, H_);
        softmax_apply_kernel<<<B_, H_>>>(t);
        // inp = CX[t] + applied @ comb_W[:, 512:]^T
        sgemm2<<<dim3(H_ / 64, B_ / 64), blk>>>(p_applied, E_, comb_W + 512, 1024, nullptr,
                                                p_CX + (size_t)t * B_ * H_, H_,
                                                p_inp, H_, B_, H_, E_);
        // gx = inp @ Wih^T + bih   [128 x 1536]
        sgemm2<<<dim3(1536 / 64, B_ / 64), blk>>>(p_inp, H_, gru_Wih, H_, gru_bih,
                                                  nullptr, 0, p_gx, 1536,
                                                  B_, 1536, H_);
        gate_kernel<<<(B_ * H_) / 256, 256>>>(t, gru_bhh);
    }

    // vocab projection + log_softmax (in place on d_out)
    sgemm2<<<dim3((V_ + 63) / 64, (T_ * B_) / 64), blk>>>(p_hs, H_, out_W, H_, out_b,
                                                          nullptr, 0, out, V_,
                                                          T_ * B_, V_, H_);
    logsoftmax_kernel<<<T_ * B_, 256, V_ * sizeof(float)>>>(out);

    // hiddens output after log-probs
    transpose_h_kernel<<<(T_ * B_ * H_) / 256, 256>>>(out + (size_t)T_ * B_ * V_);
}

// round 5
// speedup vs baseline: 1.8107x; 1.0900x over previous
#include <cuda_runtime.h>
#include <math.h>

#define B_   128
#define T_   64
#define E_   512
#define H_   512
#define V_   10000
#define FIN_ 2048
#define NBLK 128

// ---------------- scratch (device globals; no allocation) ----------------
__device__ float g_f[B_ * E_];
__device__ float g_feats[B_ * E_];
__device__ float g_h[B_ * H_];
__device__ float g_X[T_ * B_ * E_];
__device__ float g_AX[T_ * B_ * H_];
__device__ float g_CX[T_ * B_ * H_];
__device__ float g_Whcat[2048 * H_];
__device__ float g_hproj[B_ * 2048];
__device__ float g_applied[B_ * E_];
__device__ float g_inp[B_ * H_];
__device__ float g_gx[B_ * 3 * H_];
__device__ float g_hs[T_ * B_ * H_];

__device__ unsigned int g_bar_count = 0;
__device__ unsigned int g_bar_gen   = 0;

// ---------------- software grid barrier (all NBLK blocks resident) -------
__device__ __forceinline__ void grid_barrier()
{
    __syncthreads();
    if (threadIdx.x == 0) {
        __threadfence();
        unsigned int gen = atomicAdd(&g_bar_gen, 0u);   // read BEFORE arriving
        __threadfence();
        unsigned int ticket = atomicAdd(&g_bar_count, 1u);
        if (ticket == NBLK - 1) {
            atomicExch(&g_bar_count, 0u);
            __threadfence();
            atomicAdd(&g_bar_gen, 1u);                  // release
        } else {
            while (atomicAdd(&g_bar_gen, 0u) == gen) { }
        }
        __threadfence();
    }
    __syncthreads();
}

// ---------------- tile GEMM helper: TM x 64 tile, K mult of 16 ----------
template<int TM>
__device__ __forceinline__ void tile_gemm(
    const float* __restrict__ A, int lda,
    const float* __restrict__ W, int ldw,
    const float* __restrict__ bias,
    const float* __restrict__ D, int ldd,
    float* __restrict__ C, int ldc,
    int K, int rowBase, int colBase,
    float (&As)[16][33], float (&Ws)[16][65])
{
    const int tid = threadIdx.x;
    const int tx = tid & 15;
    const int ty = tid >> 4;
    constexpr int RPT = TM / 16;           // rows per thread (1 or 2)
    float acc[RPT][4];
    #pragma unroll
    for (int i = 0; i < RPT; i++)
        #pragma unroll
        for (int j = 0; j < 4; j++) acc[i][j] = 0.f;

    for (int k0 = 0; k0 < K; k0 += 16) {
        #pragma unroll
        for (int i = 0; i < (TM * 16) / 256; i++) {
            int lin = tid + i * 256;
            int r = lin >> 4, c = lin & 15;
            As[c][r] = A[(size_t)(rowBase + r) * lda + k0 + c];
        }
        #pragma unroll
        for (int i = 0; i < 4; i++) {
            int lin = tid + i * 256;
            int r = lin >> 4, c = lin & 15;
            Ws[c][r] = W[(size_t)(colBase + r) * ldw + k0 + c];
        }
        __syncthreads();
        #pragma unroll
        for (int kk = 0; kk < 16; kk++) {
            float w[4];
            #pragma unroll
            for (int j = 0; j < 4; j++) w[j] = Ws[kk][tx * 4 + j];
            #pragma unroll
            for (int i = 0; i < RPT; i++) {
                float a = As[kk][ty * RPT + i];
                #pragma unroll
                for (int j = 0; j < 4; j++) acc[i][j] += a * w[j];
            }
        }
        __syncthreads();
    }
    #pragma unroll
    for (int i = 0; i < RPT; i++) {
        int r = rowBase + ty * RPT + i;
        #pragma unroll
        for (int j = 0; j < 4; j++) {
            int c = colBase + tx * 4 + j;
            float v = acc[i][j];
            if (bias) v += bias[c];
            if (D)    v += D[(size_t)r * ldd + c];
            C[(size_t)r * ldc + c] = v;
        }
    }
}

__device__ __forceinline__ float sigmoidf_(float x) { return 1.0f / (1.0f + expf(-x)); }

// ---------------- persistent recurrence kernel ---------------------------
__global__ __launch_bounds__(256, 1) void recurrence_kernel(
    const float* __restrict__ combWa,   // comb_W + 512 (ldw 1024)
    const float* __restrict__ Wih,
    const float* __restrict__ bih,
    const float* __restrict__ bhh)
{
    __shared__ float As[16][33];
    __shared__ float Ws[16][65];
    __shared__ float red[256];
    const int bid = blockIdx.x;
    const int tid = threadIdx.x;

    for (int t = 0; t < T_; t++) {
        // P1: hproj[128,2048] = h @ Whcat^T ; 4x32 tiles of 32x64
        {
            int tm = bid >> 5, tn = bid & 31;
            tile_gemm<32>(g_h, H_, g_Whcat, H_, nullptr, nullptr, 0,
                          g_hproj, 2048, H_, tm * 32, tn * 64, As, Ws);
        }
        grid_barrier();

        // P2: softmax over (AX[t] + hproj[:, :512]) row bid, apply to feats
        {
            const int b = bid;
            const float* ax = g_AX + ((size_t)t * B_ + b) * H_;
            const float* hp = g_hproj + (size_t)b * 2048;
            float v0 = ax[tid]       + hp[tid];
            float v1 = ax[tid + 256] + hp[tid + 256];
            red[tid] = fmaxf(v0, v1);
            __syncthreads();
            for (int s = 128; s > 0; s >>= 1) {
                if (tid < s) red[tid] = fmaxf(red[tid], red[tid + s]);
                __syncthreads();
            }
            float mx = red[0];
            __syncthreads();
            float e0 = expf(v0 - mx), e1 = expf(v1 - mx);
            red[tid] = e0 + e1;
            __syncthreads();
            for (int s = 128; s > 0; s >>= 1) {
                if (tid < s) red[tid] += red[tid + s];
                __syncthreads();
            }
            float inv = 1.0f / red[0];
            __syncthreads();
            g_applied[b * E_ + tid]       = g_feats[b * E_ + tid]       * (e0 * inv);
            g_applied[b * E_ + tid + 256] = g_feats[b * E_ + tid + 256] * (e1 * inv);
        }
        grid_barrier();

        // P3: inp[128,512] = CX[t] + applied @ combWa^T ; 8x8 tiles of 16x64
        if (bid < 64) {
            int tm = bid >> 3, tn = bid & 7;
            tile_gemm<16>(g_applied, E_, combWa, 1024, nullptr,
                          g_CX + (size_t)t * B_ * H_, H_,
                          g_inp, H_, E_, tm * 16, tn * 64, As, Ws);
        }
        grid_barrier();

        // P4: gx[128,1536] = inp @ Wih^T + bih ; 4x24 tiles of 32x64
        if (bid < 96) {
            int tm = bid / 24, tn = bid % 24;
            tile_gemm<32>(g_inp, H_, Wih, H_, bih, nullptr, 0,
                          g_gx, 1536, H_, tm * 32, tn * 64, As, Ws);
        }
        grid_barrier();

        // P5: GRU gates, row bid
        {
            const int b = bid;
            const float* gx = g_gx + (size_t)b * 1536;
            const float* hp = g_hproj + (size_t)b * 2048 + 512;
            #pragma unroll
            for (int u = 0; u < 2; u++) {
                int j = tid + u * 256;
                float r = sigmoidf_(gx[j]        + hp[j]        + bhh[j]);
                float z = sigmoidf_(gx[512 + j]  + hp[512 + j]  + bhh[512 + j]);
                float n = tanhf(gx[1024 + j] + r * (hp[1024 + j] + bhh[1024 + j]));
                float hprev = g_h[b * H_ + j];
                float h = (1.0f - z) * n + z * hprev;
                g_h[b * H_ + j] = h;
                g_hs[(size_t)t * B_ * H_ + b * H_ + j] = h;
            }
        }
        grid_barrier();
    }
}

// ---------------- generic SGEMM (big shapes): C = A@W^T (+bias)(+D) ------
#define BM 64
#define BN 64
#define BK 16

__global__ __launch_bounds__(256) void sgemm2(
    const float* __restrict__ A, int lda,
    const float* __restrict__ W, int ldw,
    const float* __restrict__ bias,
    const float* __restrict__ D, int ldd,
    float* __restrict__ C, int ldc,
    int M, int N, int K)
{
    __shared__ float As[BK][BM + 1];
    __shared__ float Ws[BK][BN + 1];

    const int tid = threadIdx.x;
    const int tx = tid & 15;
    const int ty = tid >> 4;
    const int rowBase = blockIdx.y * BM;
    const int colBase = blockIdx.x * BN;

    float acc[4][4] = {};

    for (int k0 = 0; k0 < K; k0 += BK) {
        #pragma unroll
        for (int i = 0; i < 4; i++) {
            int lin = tid + i * 256;
            int r = lin >> 4;
            int c = lin & 15;
            int ar = rowBase + r;
            As[c][r] = (ar < M) ? A[(size_t)ar * lda + k0 + c] : 0.f;
            int wr = colBase + r;
            Ws[c][r] = (wr < N) ? W[(size_t)wr * ldw + k0 + c] : 0.f;
        }
        __syncthreads();
        #pragma unroll
        for (int kk = 0; kk < BK; kk++) {
            float a[4], w[4];
            #pragma unroll
            for (int i = 0; i < 4; i++) a[i] = As[kk][ty * 4 + i];
            #pragma unroll
            for (int j = 0; j < 4; j++) w[j] = Ws[kk][tx * 4 + j];
            #pragma unroll
            for (int i = 0; i < 4; i++)
                #pragma unroll
                for (int j = 0; j < 4; j++)
                    acc[i][j] += a[i] * w[j];
        }
        __syncthreads();
    }

    #pragma unroll
    for (int i = 0; i < 4; i++) {
        int r = rowBase + ty * 4 + i;
        if (r >= M) continue;
        #pragma unroll
        for (int j = 0; j < 4; j++) {
            int c = colBase + tx * 4 + j;
            if (c < N) {
                float v = acc[i][j];
                if (bias) v += bias[c];
                if (D)    v += D[(size_t)r * ldd + c];
                C[(size_t)r * ldc + c] = v;
            }
        }
    }
}

// ---------------- BatchNorm1d (training mode) ----------------------------
__global__ void bn_kernel(const float* __restrict__ gamma, const float* __restrict__ beta)
{
    int e = blockIdx.x;
    int b = threadIdx.x;
    float v = g_f[b * E_ + e];
    __shared__ float red[B_];
    __shared__ float mu_s, var_s;

    red[b] = v;
    __syncthreads();
    for (int s = B_ / 2; s > 0; s >>= 1) {
        if (b < s) red[b] += red[b + s];
        __syncthreads();
    }
    if (b == 0) mu_s = red[0] * (1.0f / B_);
    __syncthreads();
    float d = v - mu_s;
    red[b] = d * d;
    __syncthreads();
    for (int s = B_ / 2; s > 0; s >>= 1) {
        if (b < s) red[b] += red[b + s];
        __syncthreads();
    }
    if (b == 0) var_s = red[0] * (1.0f / B_);
    __syncthreads();
    g_feats[b * E_ + e] = gamma[e] * d * rsqrtf(var_s + 1e-5f) + beta[e];
}

// ---------------- build X for all steps ----------------------------------
__global__ void build_X_kernel(const float* __restrict__ embed_W,
                               const int* __restrict__ captions)
{
    int idx = blockIdx.x * blockDim.x + threadIdx.x;
    int t = idx >> 16;
    int rem = idx & 65535;
    int b = rem >> 9;
    int e = rem & 511;
    float v;
    if (t == 0) v = g_feats[b * E_ + e];
    else        v = embed_W[(size_t)captions[b * T_ + (t - 1)] * E_ + e];
    g_X[idx] = v;
}

// ---------------- build [attn_Wh ; gru_Whh] ------------------------------
__global__ void build_Whcat_kernel(const float* __restrict__ attn_W,
                                   const float* __restrict__ gru_Whh)
{
    int idx = blockIdx.x * blockDim.x + threadIdx.x;
    int n = idx >> 9;
    int k = idx & 511;
    float v;
    if (n < 512) v = attn_W[(size_t)n * 1024 + 512 + k];
    else         v = gru_Whh[(size_t)(n - 512) * 512 + k];
    g_Whcat[idx] = v;
}

// ---------------- log_softmax ---------------------------------------------
__global__ void logsoftmax_kernel(float* __restrict__ out)
{
    extern __shared__ float row[];
    __shared__ float red[256];
    __shared__ float mx_s, lse_s;
    int r = blockIdx.x;
    int tid = threadIdx.x;
    float* p = out + (size_t)r * V_;

    float mx = -3.4e38f;
    for (int i = tid; i < V_; i += 256) {
        float v = p[i];
        row[i] = v;
        mx = fmaxf(mx, v);
    }
    red[tid] = mx;
    __syncthreads();
    for (int s = 128; s > 0; s >>= 1) {
        if (tid < s) red[tid] = fmaxf(red[tid], red[tid + s]);
        __syncthreads();
    }
    if (tid == 0) mx_s = red[0];
    __syncthreads();

    float sum = 0.f;
    for (int i = tid; i < V_; i += 256) sum += expf(row[i] - mx_s);
    red[tid] = sum;
    __syncthreads();
    for (int s = 128; s > 0; s >>= 1) {
        if (tid < s) red[tid] += red[tid + s];
        __syncthreads();
    }
    if (tid == 0) lse_s = mx_s + logf(red[0]);
    __syncthreads();

    for (int i = tid; i < V_; i += 256) p[i] = row[i] - lse_s;
}

// ---------------- transpose hs [T,B,H] -> [B,T,H] ------------------------
__global__ void transpose_h_kernel(float* __restrict__ out2)
{
    int idx = blockIdx.x * blockDim.x + threadIdx.x;
    int j = idx & 511;
    int b = (idx >> 9) & 127;
    int t = idx >> 16;
    out2[((size_t)b * T_ + t) * H_ + j] = g_hs[idx];
}

// ---------------- host launch ---------------------------------------------
extern "C" void kernel_launch(void* const* d_in, const int* in_sizes, int n_in,
                              void* d_out, int out_size)
{
    const float* features = (const float*)d_in[0];
    const int*   captions = (const int*)d_in[1];
    const float* h0       = (const float*)d_in[2];
    const float* embed_W  = (const float*)d_in[4];
    const float* fc_W     = (const float*)d_in[5];
    const float* fc_b     = (const float*)d_in[6];
    const float* bn_gamma = (const float*)d_in[7];
    const float* bn_beta  = (const float*)d_in[8];
    const float* attn_W   = (const float*)d_in[9];
    const float* attn_b   = (const float*)d_in[10];
    const float* comb_W   = (const float*)d_in[11];
    const float* comb_b   = (const float*)d_in[12];
    const float* gru_Wih  = (const float*)d_in[13];
    const float* gru_Whh  = (const float*)d_in[14];
    const float* gru_bih  = (const float*)d_in[15];
    const float* gru_bhh  = (const float*)d_in[16];
    const float* out_W    = (const float*)d_in[17];
    const float* out_b    = (const float*)d_in[18];
    float* out = (float*)d_out;

    float *p_f, *p_h, *p_X, *p_AX, *p_CX, *p_hs;
    cudaGetSymbolAddress((void**)&p_f,  g_f);
    cudaGetSymbolAddress((void**)&p_h,  g_h);
    cudaGetSymbolAddress((void**)&p_X,  g_X);
    cudaGetSymbolAddress((void**)&p_AX, g_AX);
    cudaGetSymbolAddress((void**)&p_CX, g_CX);
    cudaGetSymbolAddress((void**)&p_hs, g_hs);

    cudaMemcpyAsync(p_h, h0, (size_t)B_ * H_ * sizeof(float), cudaMemcpyDeviceToDevice);

    dim3 blk(256);

    // fc + batchnorm
    sgemm2<<<dim3(E_ / 64, B_ / 64), blk>>>(features, FIN_, fc_W, FIN_, fc_b,
                                            nullptr, 0, p_f, E_, B_, E_, FIN_);
    bn_kernel<<<E_, B_>>>(bn_gamma, bn_beta);

    // hoisted x-dependent work
    build_X_kernel<<<(T_ * B_ * E_) / 256, 256>>>(embed_W, captions);
    build_Whcat_kernel<<<(2048 * H_) / 256, 256>>>(attn_W, gru_Whh);
    sgemm2<<<dim3(H_ / 64, (T_ * B_) / 64), blk>>>(p_X, E_, attn_W, 1024, attn_b,
                                                   nullptr, 0, p_AX, H_,
                                                   T_ * B_, H_, E_);
    sgemm2<<<dim3(H_ / 64, (T_ * B_) / 64), blk>>>(p_X, E_, comb_W, 1024, comb_b,
                                                   nullptr, 0, p_CX, H_,
                                                   T_ * B_, H_, E_);

    // fused persistent recurrence: ONE launch for all 64 steps
    recurrence_kernel<<<NBLK, 256>>>(comb_W + 512, gru_Wih, gru_bih, gru_bhh);

    // vocab projection + log_softmax
    sgemm2<<<dim3((V_ + 63) / 64, (T_ * B_) / 64), blk>>>(p_hs, H_, out_W, H_, out_b,
                                                          nullptr, 0, out, V_,
                                                          T_ * B_, V_, H_);
    logsoftmax_kernel<<<T_ * B_, 256, V_ * sizeof(float)>>>(out);

    transpose_h_kernel<<<(T_ * B_ * H_) / 256, 256>>>(out + (size_t)T_ * B_ * V_);
}

// round 6
// speedup vs baseline: 2.0986x; 1.1590x over previous
#include <cuda_runtime.h>
#include <math.h>

#define B_   128
#define T_   64
#define E_   512
#define H_   512
#define V_   10000
#define FIN_ 2048
#define NBLK 128

// ---------------- scratch (device globals; no allocation) ----------------
__device__ float g_f[B_ * E_];
__device__ float g_feats[B_ * E_];
__device__ float g_h[B_ * H_];
__device__ float g_X[T_ * B_ * E_];
__device__ float g_AX[T_ * B_ * H_];
__device__ float g_CX[T_ * B_ * H_];
__device__ float g_Whcat[2048 * H_];
__device__ float g_hproj[B_ * 2048];
__device__ float g_applied[B_ * E_];
__device__ float g_inp[B_ * H_];
__device__ float g_gx[B_ * 3 * H_];
__device__ float g_hs[T_ * B_ * H_];

// barrier state: count and release on SEPARATE 256B lines (no sector sharing)
__device__ __align__(256) unsigned int g_bar_count[64];
__device__ __align__(256) unsigned int g_bar_release[64];

// ---------------- software grid barrier (all NBLK blocks resident) -------
// Arrival: one atomicAdd per block. Wait: plain volatile LOAD polling (no RMW
// serialization at L2). Relative-generation compare -> replay-safe.
__device__ __forceinline__ void grid_barrier()
{
    __syncthreads();
    if (threadIdx.x == 0) {
        volatile unsigned int* rel = g_bar_release;
        unsigned int before = rel[0];
        __threadfence();
        unsigned int t = atomicAdd(&g_bar_count[0], 1u);
        if (t == NBLK - 1) {
            atomicExch(&g_bar_count[0], 0u);
            __threadfence();
            atomicAdd(&g_bar_release[0], 1u);
        } else {
            while (rel[0] == before) { }
        }
        __threadfence();
    }
    __syncthreads();
}

// ---------------- tile GEMM helper: TM x 64 tile, K mult of 16 ----------
template<int TM>
__device__ __forceinline__ void tile_gemm(
    const float* __restrict__ A, int lda,
    const float* __restrict__ W, int ldw,
    const float* __restrict__ bias,
    const float* __restrict__ D, int ldd,
    float* __restrict__ C, int ldc,
    int K, int rowBase, int colBase,
    float (&As)[16][33], float (&Ws)[16][65])
{
    const int tid = threadIdx.x;
    const int tx = tid & 15;
    const int ty = tid >> 4;
    constexpr int RPT = TM / 16;
    float acc[RPT][4];
    #pragma unroll
    for (int i = 0; i < RPT; i++)
        #pragma unroll
        for (int j = 0; j < 4; j++) acc[i][j] = 0.f;

    for (int k0 = 0; k0 < K; k0 += 16) {
        #pragma unroll
        for (int i = 0; i < (TM * 16) / 256; i++) {
            int lin = tid + i * 256;
            int r = lin >> 4, c = lin & 15;
            As[c][r] = A[(size_t)(rowBase + r) * lda + k0 + c];
        }
        #pragma unroll
        for (int i = 0; i < 4; i++) {
            int lin = tid + i * 256;
            int r = lin >> 4, c = lin & 15;
            Ws[c][r] = W[(size_t)(colBase + r) * ldw + k0 + c];
        }
        __syncthreads();
        #pragma unroll
        for (int kk = 0; kk < 16; kk++) {
            float w[4];
            #pragma unroll
            for (int j = 0; j < 4; j++) w[j] = Ws[kk][tx * 4 + j];
            #pragma unroll
            for (int i = 0; i < RPT; i++) {
                float a = As[kk][ty * RPT + i];
                #pragma unroll
                for (int j = 0; j < 4; j++) acc[i][j] += a * w[j];
            }
        }
        __syncthreads();
    }
    #pragma unroll
    for (int i = 0; i < RPT; i++) {
        int r = rowBase + ty * RPT + i;
        #pragma unroll
        for (int j = 0; j < 4; j++) {
            int c = colBase + tx * 4 + j;
            float v = acc[i][j];
            if (bias) v += bias[c];
            if (D)    v += D[(size_t)r * ldd + c];
            C[(size_t)r * ldc + c] = v;
        }
    }
}

__device__ __forceinline__ float sigmoidf_(float x) { return 1.0f / (1.0f + expf(-x)); }

// ---------------- persistent recurrence kernel ---------------------------
__global__ __launch_bounds__(256, 1) void recurrence_kernel(
    const float* __restrict__ combWa,   // comb_W + 512 (ldw 1024)
    const float* __restrict__ Wih,
    const float* __restrict__ bih,
    const float* __restrict__ bhh)
{
    __shared__ float As[16][33];
    __shared__ float Ws[16][65];
    __shared__ float red[256];
    const int bid = blockIdx.x;
    const int tid = threadIdx.x;

    for (int t = 0; t < T_; t++) {
        // P1: hproj[128,2048] = h @ Whcat^T ; 4x32 tiles of 32x64
        {
            int tm = bid >> 5, tn = bid & 31;
            tile_gemm<32>(g_h, H_, g_Whcat, H_, nullptr, nullptr, 0,
                          g_hproj, 2048, H_, tm * 32, tn * 64, As, Ws);
        }
        grid_barrier();

        // P2: softmax over (AX[t] + hproj[:, :512]) row bid, apply to feats
        {
            const int b = bid;
            const float* ax = g_AX + ((size_t)t * B_ + b) * H_;
            const float* hp = g_hproj + (size_t)b * 2048;
            float v0 = ax[tid]       + hp[tid];
            float v1 = ax[tid + 256] + hp[tid + 256];
            red[tid] = fmaxf(v0, v1);
            __syncthreads();
            for (int s = 128; s > 0; s >>= 1) {
                if (tid < s) red[tid] = fmaxf(red[tid], red[tid + s]);
                __syncthreads();
            }
            float mx = red[0];
            __syncthreads();
            float e0 = expf(v0 - mx), e1 = expf(v1 - mx);
            red[tid] = e0 + e1;
            __syncthreads();
            for (int s = 128; s > 0; s >>= 1) {
                if (tid < s) red[tid] += red[tid + s];
                __syncthreads();
            }
            float inv = 1.0f / red[0];
            __syncthreads();
            g_applied[b * E_ + tid]       = g_feats[b * E_ + tid]       * (e0 * inv);
            g_applied[b * E_ + tid + 256] = g_feats[b * E_ + tid + 256] * (e1 * inv);
        }
        grid_barrier();

        // P3: inp[128,512] = CX[t] + applied @ combWa^T ; 8x8 tiles of 16x64
        if (bid < 64) {
            int tm = bid >> 3, tn = bid & 7;
            tile_gemm<16>(g_applied, E_, combWa, 1024, nullptr,
                          g_CX + (size_t)t * B_ * H_, H_,
                          g_inp, H_, E_, tm * 16, tn * 64, As, Ws);
        }
        grid_barrier();

        // P4: gx[128,1536] = inp @ Wih^T + bih ; 4x24 tiles of 32x64
        if (bid < 96) {
            int tm = bid / 24, tn = bid % 24;
            tile_gemm<32>(g_inp, H_, Wih, H_, bih, nullptr, 0,
                          g_gx, 1536, H_, tm * 32, tn * 64, As, Ws);
        }
        grid_barrier();

        // P5: GRU gates, row bid
        {
            const int b = bid;
            const float* gx = g_gx + (size_t)b * 1536;
            const float* hp = g_hproj + (size_t)b * 2048 + 512;
            #pragma unroll
            for (int u = 0; u < 2; u++) {
                int j = tid + u * 256;
                float r = sigmoidf_(gx[j]        + hp[j]        + bhh[j]);
                float z = sigmoidf_(gx[512 + j]  + hp[512 + j]  + bhh[512 + j]);
                float n = tanhf(gx[1024 + j] + r * (hp[1024 + j] + bhh[1024 + j]));
                float hprev = g_h[b * H_ + j];
                float h = (1.0f - z) * n + z * hprev;
                g_h[b * H_ + j] = h;
                g_hs[(size_t)t * B_ * H_ + b * H_ + j] = h;
            }
        }
        grid_barrier();
    }
}

// ---------------- generic SGEMM (small shapes) ---------------------------
#define BM 64
#define BN 64
#define BK 16

__global__ __launch_bounds__(256) void sgemm2(
    const float* __restrict__ A, int lda,
    const float* __restrict__ W, int ldw,
    const float* __restrict__ bias,
    const float* __restrict__ D, int ldd,
    float* __restrict__ C, int ldc,
    int M, int N, int K)
{
    __shared__ float As[BK][BM + 1];
    __shared__ float Ws[BK][BN + 1];

    const int tid = threadIdx.x;
    const int tx = tid & 15;
    const int ty = tid >> 4;
    const int rowBase = blockIdx.y * BM;
    const int colBase = blockIdx.x * BN;

    float acc[4][4] = {};

    for (int k0 = 0; k0 < K; k0 += BK) {
        #pragma unroll
        for (int i = 0; i < 4; i++) {
            int lin = tid + i * 256;
            int r = lin >> 4;
            int c = lin & 15;
            int ar = rowBase + r;
            As[c][r] = (ar < M) ? A[(size_t)ar * lda + k0 + c] : 0.f;
            int wr = colBase + r;
            Ws[c][r] = (wr < N) ? W[(size_t)wr * ldw + k0 + c] : 0.f;
        }
        __syncthreads();
        #pragma unroll
        for (int kk = 0; kk < BK; kk++) {
            float a[4], w[4];
            #pragma unroll
            for (int i = 0; i < 4; i++) a[i] = As[kk][ty * 4 + i];
            #pragma unroll
            for (int j = 0; j < 4; j++) w[j] = Ws[kk][tx * 4 + j];
            #pragma unroll
            for (int i = 0; i < 4; i++)
                #pragma unroll
                for (int j = 0; j < 4; j++)
                    acc[i][j] += a[i] * w[j];
        }
        __syncthreads();
    }

    #pragma unroll
    for (int i = 0; i < 4; i++) {
        int r = rowBase + ty * 4 + i;
        if (r >= M) continue;
        #pragma unroll
        for (int j = 0; j < 4; j++) {
            int c = colBase + tx * 4 + j;
            if (c < N) {
                float v = acc[i][j];
                if (bias) v += bias[c];
                if (D)    v += D[(size_t)r * ldd + c];
                C[(size_t)r * ldc + c] = v;
            }
        }
    }
}

// ---------------- big SGEMM: BM=128, BN=64, 8x4 micro (M mult of 128) ----
#define GBM 128
#define GBN 64

__global__ __launch_bounds__(256) void sgemm_big(
    const float* __restrict__ A, int lda,
    const float* __restrict__ W, int ldw,
    const float* __restrict__ bias,
    float* __restrict__ C, int ldc,
    int M, int N, int K)
{
    __shared__ float As[16][GBM + 4];
    __shared__ float Ws[16][GBN + 4];

    const int tid = threadIdx.x;
    const int tx = tid & 15;         // 16 groups of 4 cols
    const int ty = tid >> 4;         // 16 groups of 8 rows
    const int rowBase = blockIdx.y * GBM;
    const int colBase = blockIdx.x * GBN;

    float acc[8][4] = {};

    for (int k0 = 0; k0 < K; k0 += 16) {
        #pragma unroll
        for (int i = 0; i < 8; i++) {
            int lin = tid + i * 256;
            int r = lin >> 4, c = lin & 15;
            As[c][r] = A[(size_t)(rowBase + r) * lda + k0 + c];
        }
        #pragma unroll
        for (int i = 0; i < 4; i++) {
            int lin = tid + i * 256;
            int r = lin >> 4, c = lin & 15;
            int wr = colBase + r;
            Ws[c][r] = (wr < N) ? W[(size_t)wr * ldw + k0 + c] : 0.f;
        }
        __syncthreads();
        #pragma unroll
        for (int kk = 0; kk < 16; kk++) {
            float a[8], w[4];
            #pragma unroll
            for (int j = 0; j < 4; j++) w[j] = Ws[kk][tx * 4 + j];
            #pragma unroll
            for (int i = 0; i < 8; i++) a[i] = As[kk][ty * 8 + i];
            #pragma unroll
            for (int i = 0; i < 8; i++)
                #pragma unroll
                for (int j = 0; j < 4; j++)
                    acc[i][j] += a[i] * w[j];
        }
        __syncthreads();
    }

    #pragma unroll
    for (int i = 0; i < 8; i++) {
        int r = rowBase + ty * 8 + i;
        #pragma unroll
        for (int j = 0; j < 4; j++) {
            int c = colBase + tx * 4 + j;
            if (c < N) {
                float v = acc[i][j];
                if (bias) v += bias[c];
                C[(size_t)r * ldc + c] = v;
            }
        }
    }
}

// ---------------- BatchNorm1d (training mode) ----------------------------
__global__ void bn_kernel(const float* __restrict__ gamma, const float* __restrict__ beta)
{
    int e = blockIdx.x;
    int b = threadIdx.x;
    float v = g_f[b * E_ + e];
    __shared__ float red[B_];
    __shared__ float mu_s, var_s;

    red[b] = v;
    __syncthreads();
    for (int s = B_ / 2; s > 0; s >>= 1) {
        if (b < s) red[b] += red[b + s];
        __syncthreads();
    }
    if (b == 0) mu_s = red[0] * (1.0f / B_);
    __syncthreads();
    float d = v - mu_s;
    red[b] = d * d;
    __syncthreads();
    for (int s = B_ / 2; s > 0; s >>= 1) {
        if (b < s) red[b] += red[b + s];
        __syncthreads();
    }
    if (b == 0) var_s = red[0] * (1.0f / B_);
    __syncthreads();
    g_feats[b * E_ + e] = gamma[e] * d * rsqrtf(var_s + 1e-5f) + beta[e];
}

// ---------------- build X for all steps ----------------------------------
__global__ void build_X_kernel(const float* __restrict__ embed_W,
                               const int* __restrict__ captions)
{
    int idx = blockIdx.x * blockDim.x + threadIdx.x;
    int t = idx >> 16;
    int rem = idx & 65535;
    int b = rem >> 9;
    int e = rem & 511;
    float v;
    if (t == 0) v = g_feats[b * E_ + e];
    else        v = embed_W[(size_t)captions[b * T_ + (t - 1)] * E_ + e];
    g_X[idx] = v;
}

// ---------------- build [attn_Wh ; gru_Whh] ------------------------------
__global__ void build_Whcat_kernel(const float* __restrict__ attn_W,
                                   const float* __restrict__ gru_Whh)
{
    int idx = blockIdx.x * blockDim.x + threadIdx.x;
    int n = idx >> 9;
    int k = idx & 511;
    float v;
    if (n < 512) v = attn_W[(size_t)n * 1024 + 512 + k];
    else         v = gru_Whh[(size_t)(n - 512) * 512 + k];
    g_Whcat[idx] = v;
}

// ---------------- log_softmax ---------------------------------------------
__global__ void logsoftmax_kernel(float* __restrict__ out)
{
    extern __shared__ float row[];
    __shared__ float red[256];
    __shared__ float mx_s, lse_s;
    int r = blockIdx.x;
    int tid = threadIdx.x;
    float* p = out + (size_t)r * V_;

    float mx = -3.4e38f;
    for (int i = tid; i < V_; i += 256) {
        float v = p[i];
        row[i] = v;
        mx = fmaxf(mx, v);
    }
    red[tid] = mx;
    __syncthreads();
    for (int s = 128; s > 0; s >>= 1) {
        if (tid < s) red[tid] = fmaxf(red[tid], red[tid + s]);
        __syncthreads();
    }
    if (tid == 0) mx_s = red[0];
    __syncthreads();

    float sum = 0.f;
    for (int i = tid; i < V_; i += 256) sum += expf(row[i] - mx_s);
    red[tid] = sum;
    __syncthreads();
    for (int s = 128; s > 0; s >>= 1) {
        if (tid < s) red[tid] += red[tid + s];
        __syncthreads();
    }
    if (tid == 0) lse_s = mx_s + logf(red[0]);
    __syncthreads();

    for (int i = tid; i < V_; i += 256) p[i] = row[i] - lse_s;
}

// ---------------- transpose hs [T,B,H] -> [B,T,H] ------------------------
__global__ void transpose_h_kernel(float* __restrict__ out2)
{
    int idx = blockIdx.x * blockDim.x + threadIdx.x;
    int j = idx & 511;
    int b = (idx >> 9) & 127;
    int t = idx >> 16;
    out2[((size_t)b * T_ + t) * H_ + j] = g_hs[idx];
}

// ---------------- host launch ---------------------------------------------
extern "C" void kernel_launch(void* const* d_in, const int* in_sizes, int n_in,
                              void* d_out, int out_size)
{
    const float* features = (const float*)d_in[0];
    const int*   captions = (const int*)d_in[1];
    const float* h0       = (const float*)d_in[2];
    const float* embed_W  = (const float*)d_in[4];
    const float* fc_W     = (const float*)d_in[5];
    const float* fc_b     = (const float*)d_in[6];
    const float* bn_gamma = (const float*)d_in[7];
    const float* bn_beta  = (const float*)d_in[8];
    const float* attn_W   = (const float*)d_in[9];
    const float* attn_b   = (const float*)d_in[10];
    const float* comb_W   = (const float*)d_in[11];
    const float* comb_b   = (const float*)d_in[12];
    const float* gru_Wih  = (const float*)d_in[13];
    const float* gru_Whh  = (const float*)d_in[14];
    const float* gru_bih  = (const float*)d_in[15];
    const float* gru_bhh  = (const float*)d_in[16];
    const float* out_W    = (const float*)d_in[17];
    const float* out_b    = (const float*)d_in[18];
    float* out = (float*)d_out;

    float *p_f, *p_h, *p_X, *p_AX, *p_CX, *p_hs;
    cudaGetSymbolAddress((void**)&p_f,  g_f);
    cudaGetSymbolAddress((void**)&p_h,  g_h);
    cudaGetSymbolAddress((void**)&p_X,  g_X);
    cudaGetSymbolAddress((void**)&p_AX, g_AX);
    cudaGetSymbolAddress((void**)&p_CX, g_CX);
    cudaGetSymbolAddress((void**)&p_hs, g_hs);

    cudaMemcpyAsync(p_h, h0, (size_t)B_ * H_ * sizeof(float), cudaMemcpyDeviceToDevice);

    dim3 blk(256);

    // fc + batchnorm
    sgemm2<<<dim3(E_ / 64, B_ / 64), blk>>>(features, FIN_, fc_W, FIN_, fc_b,
                                            nullptr, 0, p_f, E_, B_, E_, FIN_);
    bn_kernel<<<E_, B_>>>(bn_gamma, bn_beta);

    // hoisted x-dependent work
    build_X_kernel<<<(T_ * B_ * E_) / 256, 256>>>(embed_W, captions);
    build_Whcat_kernel<<<(2048 * H_) / 256, 256>>>(attn_W, gru_Whh);
    sgemm_big<<<dim3(H_ / GBN, (T_ * B_) / GBM), blk>>>(p_X, E_, attn_W, 1024, attn_b,
                                                        p_AX, H_, T_ * B_, H_, E_);
    sgemm_big<<<dim3(H_ / GBN, (T_ * B_) / GBM), blk>>>(p_X, E_, comb_W, 1024, comb_b,
                                                        p_CX, H_, T_ * B_, H_, E_);

    // fused persistent recurrence: ONE launch for all 64 steps
    recurrence_kernel<<<NBLK, 256>>>(comb_W + 512, gru_Wih, gru_bih, gru_bhh);

    // vocab projection + log_softmax
    sgemm_big<<<dim3((V_ + GBN - 1) / GBN, (T_ * B_) / GBM), blk>>>(
        p_hs, H_, out_W, H_, out_b, out, V_, T_ * B_, V_, H_);
    logsoftmax_kernel<<<T_ * B_, 256, V_ * sizeof(float)>>>(out);

    transpose_h_kernel<<<(T_ * B_ * H_) / 256, 256>>>(out + (size_t)T_ * B_ * V_);
}

// round 9
// speedup vs baseline: 2.5637x; 1.2216x over previous
#include <cuda_runtime.h>
#include <math.h>

#define B_   128
#define T_   64
#define E_   512
#define H_   512
#define V_   10000
#define FIN_ 2048
#define NBLK 256

// ---------------- scratch (device globals; no allocation) ----------------
__device__ float g_f[B_ * E_];
__device__ float g_feats[B_ * E_];
__device__ float g_h[B_ * H_];
__device__ float g_X[T_ * B_ * E_];
__device__ float g_AX[T_ * B_ * H_];
__device__ float g_CX[T_ * B_ * H_];
__device__ float g_Whcat[2048 * H_];
__device__ float g_hproj[B_ * 2048];
__device__ float g_applied[B_ * E_];
__device__ float g_inp[B_ * H_];
__device__ float g_gx[B_ * 3 * H_];
__device__ float g_hs[T_ * B_ * H_];

// barrier state on separate 256B lines
__device__ __align__(256) unsigned int g_bar_count[64];
__device__ __align__(256) unsigned int g_bar_release[64];

// ---------------- software grid barrier (all NBLK blocks resident) -------
__device__ __forceinline__ void grid_barrier()
{
    __syncthreads();
    if (threadIdx.x == 0) {
        volatile unsigned int* rel = g_bar_release;
        unsigned int before = rel[0];
        __threadfence();
        unsigned int t = atomicAdd(&g_bar_count[0], 1u);
        if (t == NBLK - 1) {
            atomicExch(&g_bar_count[0], 0u);
            __threadfence();
            atomicAdd(&g_bar_release[0], 1u);
        } else {
            while (rel[0] == before) { }
        }
        __threadfence();
    }
    __syncthreads();
}

// ---------------- double-buffered 16x64 tile GEMM (K mult of 16) ---------
// 256 threads. C tile = 16 rows x 64 cols. One __syncthreads per K-iter.
__device__ __forceinline__ void tile_gemm16_db(
    const float* __restrict__ A, int lda,
    const float* __restrict__ W, int ldw,
    const float* __restrict__ bias,
    const float* __restrict__ D, int ldd,
    float* __restrict__ C, int ldc,
    int K, int rowBase, int colBase,
    float (&As)[2][16][20], float (&Ws)[2][16][68])
{
    const int tid = threadIdx.x;
    const int tx = tid & 15;           // col group (4 cols)
    const int ty = tid >> 4;           // row (0..15)
    const int lr = tid >> 4;           // load row for A (0..15)
    const int lc = tid & 15;           // load col (k within tile)

    float acc[4] = {0.f, 0.f, 0.f, 0.f};

    // prologue: load k-tile 0 into regs
    float a_pre = A[(size_t)(rowBase + lr) * lda + lc];
    float w_pre[4];
    #pragma unroll
    for (int i = 0; i < 4; i++) {
        int r = (tid + i * 256) >> 4;
        w_pre[i] = W[(size_t)(colBase + r) * ldw + lc];
    }

    int buf = 0;
    for (int k0 = 0; k0 < K; k0 += 16) {
        // store prefetched tile
        As[buf][lc][lr] = a_pre;
        #pragma unroll
        for (int i = 0; i < 4; i++) {
            int r = (tid + i * 256) >> 4;
            Ws[buf][lc][r] = w_pre[i];
        }
        __syncthreads();
        // prefetch next tile
        if (k0 + 16 < K) {
            a_pre = A[(size_t)(rowBase + lr) * lda + k0 + 16 + lc];
            #pragma unroll
            for (int i = 0; i < 4; i++) {
                int r = (tid + i * 256) >> 4;
                w_pre[i] = W[(size_t)(colBase + r) * ldw + k0 + 16 + lc];
            }
        }
        // compute from current buffer
        #pragma unroll
        for (int kk = 0; kk < 16; kk++) {
            float a = As[buf][kk][ty];
            float w0 = Ws[buf][kk][tx * 4 + 0];
            float w1 = Ws[buf][kk][tx * 4 + 1];
            float w2 = Ws[buf][kk][tx * 4 + 2];
            float w3 = Ws[buf][kk][tx * 4 + 3];
            acc[0] += a * w0; acc[1] += a * w1;
            acc[2] += a * w2; acc[3] += a * w3;
        }
        buf ^= 1;
    }

    int r = rowBase + ty;
    #pragma unroll
    for (int j = 0; j < 4; j++) {
        int c = colBase + tx * 4 + j;
        float v = acc[j];
        if (bias) v += bias[c];
        if (D)    v += D[(size_t)r * ldd + c];
        C[(size_t)r * ldc + c] = v;
    }
}

__device__ __forceinline__ float sigmoidf_(float x) { return 1.0f / (1.0f + expf(-x)); }

// ---------------- persistent recurrence kernel: 256 blocks x 256 thr -----
__global__ __launch_bounds__(256, 2) void recurrence_kernel(
    const float* __restrict__ combWa,   // comb_W + 512 (ldw 1024)
    const float* __restrict__ Wih,
    const float* __restrict__ bih,
    const float* __restrict__ bhh)
{
    __shared__ float As[2][16][20];
    __shared__ float Ws[2][16][68];
    __shared__ float red[256];
    const int bid = blockIdx.x;
    const int tid = threadIdx.x;

    for (int t = 0; t < T_; t++) {
        // P1: hproj[128,2048] = h @ Whcat^T ; 8x32 = 256 tiles of 16x64
        {
            int tm = bid >> 5, tn = bid & 31;
            tile_gemm16_db(g_h, H_, g_Whcat, H_, nullptr, nullptr, 0,
                           g_hproj, 2048, H_, tm * 16, tn * 64, As, Ws);
        }
        grid_barrier();

        // P2: softmax over (AX[t] + hproj[:, :512]) row bid, apply to feats
        if (bid < B_) {
            const int b = bid;
            const float* ax = g_AX + ((size_t)t * B_ + b) * H_;
            const float* hp = g_hproj + (size_t)b * 2048;
            float v0 = ax[tid]       + hp[tid];
            float v1 = ax[tid + 256] + hp[tid + 256];
            red[tid] = fmaxf(v0, v1);
            __syncthreads();
            for (int s = 128; s > 0; s >>= 1) {
                if (tid < s) red[tid] = fmaxf(red[tid], red[tid + s]);
                __syncthreads();
            }
            float mx = red[0];
            __syncthreads();
            float e0 = expf(v0 - mx), e1 = expf(v1 - mx);
            red[tid] = e0 + e1;
            __syncthreads();
            for (int s = 128; s > 0; s >>= 1) {
                if (tid < s) red[tid] += red[tid + s];
                __syncthreads();
            }
            float inv = 1.0f / red[0];
            __syncthreads();
            g_applied[b * E_ + tid]       = g_feats[b * E_ + tid]       * (e0 * inv);
            g_applied[b * E_ + tid + 256] = g_feats[b * E_ + tid + 256] * (e1 * inv);
        }
        grid_barrier();

        // P3: inp[128,512] = CX[t] + applied @ combWa^T ; 8x8 = 64 tiles
        if (bid < 64) {
            int tm = bid >> 3, tn = bid & 7;
            tile_gemm16_db(g_applied, E_, combWa, 1024, nullptr,
                           g_CX + (size_t)t * B_ * H_, H_,
                           g_inp, H_, E_, tm * 16, tn * 64, As, Ws);
        }
        grid_barrier();

        // P4: gx[128,1536] = inp @ Wih^T + bih ; 8x24 = 192 tiles
        if (bid < 192) {
            int tm = bid / 24, tn = bid % 24;
            tile_gemm16_db(g_inp, H_, Wih, H_, bih, nullptr, 0,
                           g_gx, 1536, H_, tm * 16, tn * 64, As, Ws);
        }
        grid_barrier();

        // P5: GRU gates, row bid
        if (bid < B_) {
            const int b = bid;
            const float* gx = g_gx + (size_t)b * 1536;
            const float* hp = g_hproj + (size_t)b * 2048 + 512;
            #pragma unroll
            for (int u = 0; u < 2; u++) {
                int j = tid + u * 256;
                float r = sigmoidf_(gx[j]        + hp[j]        + bhh[j]);
                float z = sigmoidf_(gx[512 + j]  + hp[512 + j]  + bhh[512 + j]);
                float n = tanhf(gx[1024 + j] + r * (hp[1024 + j] + bhh[1024 + j]));
                float hprev = g_h[b * H_ + j];
                float h = (1.0f - z) * n + z * hprev;
                g_h[b * H_ + j] = h;
                g_hs[(size_t)t * B_ * H_ + b * H_ + j] = h;
            }
        }
        grid_barrier();
    }
}

// ---------------- generic SGEMM (small shapes) ---------------------------
#define BM 64
#define BN 64
#define BK 16

__global__ __launch_bounds__(256) void sgemm2(
    const float* __restrict__ A, int lda,
    const float* __restrict__ W, int ldw,
    const float* __restrict__ bias,
    const float* __restrict__ D, int ldd,
    float* __restrict__ C, int ldc,
    int M, int N, int K)
{
    __shared__ float As[BK][BM + 1];
    __shared__ float Ws[BK][BN + 1];

    const int tid = threadIdx.x;
    const int tx = tid & 15;
    const int ty = tid >> 4;
    const int rowBase = blockIdx.y * BM;
    const int colBase = blockIdx.x * BN;

    float acc[4][4] = {};

    for (int k0 = 0; k0 < K; k0 += BK) {
        #pragma unroll
        for (int i = 0; i < 4; i++) {
            int lin = tid + i * 256;
            int r = lin >> 4;
            int c = lin & 15;
            int ar = rowBase + r;
            As[c][r] = (ar < M) ? A[(size_t)ar * lda + k0 + c] : 0.f;
            int wr = colBase + r;
            Ws[c][r] = (wr < N) ? W[(size_t)wr * ldw + k0 + c] : 0.f;
        }
        __syncthreads();
        #pragma unroll
        for (int kk = 0; kk < BK; kk++) {
            float a[4], w[4];
            #pragma unroll
            for (int i = 0; i < 4; i++) a[i] = As[kk][ty * 4 + i];
            #pragma unroll
            for (int j = 0; j < 4; j++) w[j] = Ws[kk][tx * 4 + j];
            #pragma unroll
            for (int i = 0; i < 4; i++)
                #pragma unroll
                for (int j = 0; j < 4; j++)
                    acc[i][j] += a[i] * w[j];
        }
        __syncthreads();
    }

    #pragma unroll
    for (int i = 0; i < 4; i++) {
        int r = rowBase + ty * 4 + i;
        if (r >= M) continue;
        #pragma unroll
        for (int j = 0; j < 4; j++) {
            int c = colBase + tx * 4 + j;
            if (c < N) {
                float v = acc[i][j];
                if (bias) v += bias[c];
                if (D)    v += D[(size_t)r * ldd + c];
                C[(size_t)r * ldc + c] = v;
            }
        }
    }
}

// ---------------- big SGEMM: BM=128, BN=64, 8x4 micro, double-buffered ---
#define GBM 128
#define GBN 64

__global__ __launch_bounds__(256) void sgemm_big(
    const float* __restrict__ A, int lda,
    const float* __restrict__ W, int ldw,
    const float* __restrict__ bias,
    float* __restrict__ C, int ldc,
    int M, int N, int K)
{
    __shared__ float As[2][16][GBM + 4];
    __shared__ float Ws[2][16][GBN + 4];

    const int tid = threadIdx.x;
    const int tx = tid & 15;
    const int ty = tid >> 4;
    const int rowBase = blockIdx.y * GBM;
    const int colBase = blockIdx.x * GBN;
    const int lc = tid & 15;

    float acc[8][4] = {};

    // prologue
    float a_pre[8], w_pre[4];
    #pragma unroll
    for (int i = 0; i < 8; i++) {
        int r = (tid + i * 256) >> 4;
        a_pre[i] = A[(size_t)(rowBase + r) * lda + lc];
    }
    #pragma unroll
    for (int i = 0; i < 4; i++) {
        int r = (tid + i * 256) >> 4;
        int wr = colBase + r;
        w_pre[i] = (wr < N) ? W[(size_t)wr * ldw + lc] : 0.f;
    }

    int buf = 0;
    for (int k0 = 0; k0 < K; k0 += 16) {
        #pragma unroll
        for (int i = 0; i < 8; i++) {
            int r = (tid + i * 256) >> 4;
            As[buf][lc][r] = a_pre[i];
        }
        #pragma unroll
        for (int i = 0; i < 4; i++) {
            int r = (tid + i * 256) >> 4;
            Ws[buf][lc][r] = w_pre[i];
        }
        __syncthreads();
        if (k0 + 16 < K) {
            #pragma unroll
            for (int i = 0; i < 8; i++) {
                int r = (tid + i * 256) >> 4;
                a_pre[i] = A[(size_t)(rowBase + r) * lda + k0 + 16 + lc];
            }
            #pragma unroll
            for (int i = 0; i < 4; i++) {
                int r = (tid + i * 256) >> 4;
                int wr = colBase + r;
                w_pre[i] = (wr < N) ? W[(size_t)wr * ldw + k0 + 16 + lc] : 0.f;
            }
        }
        #pragma unroll
        for (int kk = 0; kk < 16; kk++) {
            float a[8], w[4];
            #pragma unroll
            for (int j = 0; j < 4; j++) w[j] = Ws[buf][kk][tx * 4 + j];
            #pragma unroll
            for (int i = 0; i < 8; i++) a[i] = As[buf][kk][ty * 8 + i];
            #pragma unroll
            for (int i = 0; i < 8; i++)
                #pragma unroll
                for (int j = 0; j < 4; j++)
                    acc[i][j] += a[i] * w[j];
        }
        buf ^= 1;
    }

    #pragma unroll
    for (int i = 0; i < 8; i++) {
        int r = rowBase + ty * 8 + i;
        #pragma unroll
        for (int j = 0; j < 4; j++) {
            int c = colBase + tx * 4 + j;
            if (c < N) {
                float v = acc[i][j];
                if (bias) v += bias[c];
                C[(size_t)r * ldc + c] = v;
            }
        }
    }
}

// ---------------- BatchNorm1d (training mode) ----------------------------
__global__ void bn_kernel(const float* __restrict__ gamma, const float* __restrict__ beta)
{
    int e = blockIdx.x;
    int b = threadIdx.x;
    float v = g_f[b * E_ + e];
    __shared__ float red[B_];
    __shared__ float mu_s, var_s;

    red[b] = v;
    __syncthreads();
    for (int s = B_ / 2; s > 0; s >>= 1) {
        if (b < s) red[b] += red[b + s];
        __syncthreads();
    }
    if (b == 0) mu_s = red[0] * (1.0f / B_);
    __syncthreads();
    float d = v - mu_s;
    red[b] = d * d;
    __syncthreads();
    for (int s = B_ / 2; s > 0; s >>= 1) {
        if (b < s) red[b] += red[b + s];
        __syncthreads();
    }
    if (b == 0) var_s = red[0] * (1.0f / B_);
    __syncthreads();
    g_feats[b * E_ + e] = gamma[e] * d * rsqrtf(var_s + 1e-5f) + beta[e];
}

// ---------------- build X for all steps ----------------------------------
__global__ void build_X_kernel(const float* __restrict__ embed_W,
                               const int* __restrict__ captions)
{
    int idx = blockIdx.x * blockDim.x + threadIdx.x;
    int t = idx >> 16;
    int rem = idx & 65535;
    int b = rem >> 9;
    int e = rem & 511;
    float v;
    if (t == 0) v = g_feats[b * E_ + e];
    else        v = embed_W[(size_t)captions[b * T_ + (t - 1)] * E_ + e];
    g_X[idx] = v;
}

// ---------------- build [attn_Wh ; gru_Whh] ------------------------------
__global__ void build_Whcat_kernel(const float* __restrict__ attn_W,
                                   const float* __restrict__ gru_Whh)
{
    int idx = blockIdx.x * blockDim.x + threadIdx.x;
    int n = idx >> 9;
    int k = idx & 511;
    float v;
    if (n < 512) v = attn_W[(size_t)n * 1024 + 512 + k];
    else         v = gru_Whh[(size_t)(n - 512) * 512 + k];
    g_Whcat[idx] = v;
}

// ---------------- log_softmax ---------------------------------------------
__global__ void logsoftmax_kernel(float* __restrict__ out)
{
    extern __shared__ float row[];
    __shared__ float red[256];
    __shared__ float mx_s, lse_s;
    int r = blockIdx.x;
    int tid = threadIdx.x;
    float* p = out + (size_t)r * V_;

    float mx = -3.4e38f;
    for (int i = tid; i < V_; i += 256) {
        float v = p[i];
        row[i] = v;
        mx = fmaxf(mx, v);
    }
    red[tid] = mx;
    __syncthreads();
    for (int s = 128; s > 0; s >>= 1) {
        if (tid < s) red[tid] = fmaxf(red[tid], red[tid + s]);
        __syncthreads();
    }
    if (tid == 0) mx_s = red[0];
    __syncthreads();

    float sum = 0.f;
    for (int i = tid; i < V_; i += 256) sum += expf(row[i] - mx_s);
    red[tid] = sum;
    __syncthreads();
    for (int s = 128; s > 0; s >>= 1) {
        if (tid < s) red[tid] += red[tid + s];
        __syncthreads();
    }
    if (tid == 0) lse_s = mx_s + logf(red[0]);
    __syncthreads();

    for (int i = tid; i < V_; i += 256) p[i] = row[i] - lse_s;
}

// ---------------- transpose hs [T,B,H] -> [B,T,H] ------------------------
__global__ void transpose_h_kernel(float* __restrict__ out2)
{
    int idx = blockIdx.x * blockDim.x + threadIdx.x;
    int j = idx & 511;
    int b = (idx >> 9) & 127;
    int t = idx >> 16;
    out2[((size_t)b * T_ + t) * H_ + j] = g_hs[idx];
}

// ---------------- host launch ---------------------------------------------
extern "C" void kernel_launch(void* const* d_in, const int* in_sizes, int n_in,
                              void* d_out, int out_size)
{
    const float* features = (const float*)d_in[0];
    const int*   captions = (const int*)d_in[1];
    const float* h0       = (const float*)d_in[2];
    const float* embed_W  = (const float*)d_in[4];
    const float* fc_W     = (const float*)d_in[5];
    const float* fc_b     = (const float*)d_in[6];
    const float* bn_gamma = (const float*)d_in[7];
    const float* bn_beta  = (const float*)d_in[8];
    const float* attn_W   = (const float*)d_in[9];
    const float* attn_b   = (const float*)d_in[10];
    const float* comb_W   = (const float*)d_in[11];
    const float* comb_b   = (const float*)d_in[12];
    const float* gru_Wih  = (const float*)d_in[13];
    const float* gru_Whh  = (const float*)d_in[14];
    const float* gru_bih  = (const float*)d_in[15];
    const float* gru_bhh  = (const float*)d_in[16];
    const float* out_W    = (const float*)d_in[17];
    const float* out_b    = (const float*)d_in[18];
    float* out = (float*)d_out;

    float *p_f, *p_h, *p_X, *p_AX, *p_CX, *p_hs;
    cudaGetSymbolAddress((void**)&p_f,  g_f);
    cudaGetSymbolAddress((void**)&p_h,  g_h);
    cudaGetSymbolAddress((void**)&p_X,  g_X);
    cudaGetSymbolAddress((void**)&p_AX, g_AX);
    cudaGetSymbolAddress((void**)&p_CX, g_CX);
    cudaGetSymbolAddress((void**)&p_hs, g_hs);

    cudaMemcpyAsync(p_h, h0, (size_t)B_ * H_ * sizeof(float), cudaMemcpyDeviceToDevice);

    dim3 blk(256);

    // fc + batchnorm
    sgemm2<<<dim3(E_ / 64, B_ / 64), blk>>>(features, FIN_, fc_W, FIN_, fc_b,
                                            nullptr, 0, p_f, E_, B_, E_, FIN_);
    bn_kernel<<<E_, B_>>>(bn_gamma, bn_beta);

    // hoisted x-dependent work
    build_X_kernel<<<(T_ * B_ * E_) / 256, 256>>>(embed_W, captions);
    build_Whcat_kernel<<<(2048 * H_) / 256, 256>>>(attn_W, gru_Whh);
    sgemm_big<<<dim3(H_ / GBN, (T_ * B_) / GBM), blk>>>(p_X, E_, attn_W, 1024, attn_b,
                                                        p_AX, H_, T_ * B_, H_, E_);
    sgemm_big<<<dim3(H_ / GBN, (T_ * B_) / GBM), blk>>>(p_X, E_, comb_W, 1024, comb_b,
                                                        p_CX, H_, T_ * B_, H_, E_);

    // fused persistent recurrence: ONE launch, 256 co-resident blocks
    recurrence_kernel<<<NBLK, 256>>>(comb_W + 512, gru_Wih, gru_bih, gru_bhh);

    // vocab projection + log_softmax
    sgemm_big<<<dim3((V_ + GBN - 1) / GBN, (T_ * B_) / GBM), blk>>>(
        p_hs, H_, out_W, H_, out_b, out, V_, T_ * B_, V_, H_);
    logsoftmax_kernel<<<T_ * B_, 256, V_ * sizeof(float)>>>(out);

    transpose_h_kernel<<<(T_ * B_ * H_) / 256, 256>>>(out + (size_t)T_ * B_ * V_);
}

// round 11
// speedup vs baseline: 3.0634x; 1.1949x over previous
#include <cuda_runtime.h>
#include <cuda_bf16.h>
#include <math.h>
#include <stdint.h>

#define B_   128
#define T_   64
#define E_   512
#define H_   512
#define V_   10000
#define FIN_ 2048
#define NBLK 256

// ---------------- scratch (device globals; no allocation) ----------------
__device__ float g_f[B_ * E_];
__device__ float g_feats[B_ * E_];
__device__ float g_h[B_ * H_];
__device__ float g_X[T_ * B_ * E_];
__device__ float g_AX[T_ * B_ * H_];
__device__ float g_CX[T_ * B_ * H_];
__device__ float g_Whcat[2048 * H_];
__device__ float g_hproj[B_ * 2048];
__device__ float g_applied[B_ * E_];
__device__ float g_inp[B_ * H_];
__device__ float g_gx[B_ * 3 * H_];
__device__ float g_hs[T_ * B_ * H_];

// bf16-split operands for the tensor-core vocab GEMM (K' = 3*512 = 1536)
__device__ __nv_bfloat16 g_A2[(size_t)T_ * B_ * 1536];   // [8192, 1536]
__device__ __nv_bfloat16 g_W2[(size_t)V_ * 1536];        // [10000, 1536]

// barrier state on separate 256B lines
__device__ __align__(256) unsigned int g_bar_count[64];
__device__ __align__(256) unsigned int g_bar_release[64];

// ---------------- software grid barrier (all NBLK blocks resident) -------
__device__ __forceinline__ void grid_barrier()
{
    __syncthreads();
    if (threadIdx.x == 0) {
        volatile unsigned int* rel = g_bar_release;
        unsigned int before = rel[0];
        __threadfence();
        unsigned int t = atomicAdd(&g_bar_count[0], 1u);
        if (t == NBLK - 1) {
            atomicExch(&g_bar_count[0], 0u);
            __threadfence();
            atomicAdd(&g_bar_release[0], 1u);
        } else {
            while (rel[0] == before) { }
        }
        __threadfence();
    }
    __syncthreads();
}

// ================= baseline-PTX tensor helpers (sm_80+) ==================
__device__ __forceinline__ uint32_t smem_u32(const void* p) {
    uint32_t a;
    asm("{ .reg .u64 t; cvta.to.shared.u64 t, %1; cvt.u32.u64 %0, t; }"
        : "=r"(a) : "l"(p));
    return a;
}

__device__ __forceinline__ void ldsm_x4(uint32_t* r, uint32_t addr) {
    asm volatile("ldmatrix.sync.aligned.m8n8.x4.shared.b16 {%0,%1,%2,%3}, [%4];"
                 : "=r"(r[0]), "=r"(r[1]), "=r"(r[2]), "=r"(r[3]) : "r"(addr));
}

__device__ __forceinline__ void mma16816(float* c, const uint32_t* a, const uint32_t* b) {
    asm volatile(
        "mma.sync.aligned.m16n8k16.row.col.f32.bf16.bf16.f32 "
        "{%0,%1,%2,%3}, {%4,%5,%6,%7}, {%8,%9}, {%0,%1,%2,%3};"
        : "+f"(c[0]), "+f"(c[1]), "+f"(c[2]), "+f"(c[3])
        : "r"(a[0]), "r"(a[1]), "r"(a[2]), "r"(a[3]), "r"(b[0]), "r"(b[1]));
}

// ---------------- vocab mma.sync GEMM: out = A2 @ W2^T + out_b -----------
// block tile 128x128, 8 warps (2m x 4n), each warp 64x32. K chunks of 32,
// double-buffered SMEM, stride 40 bf16 (80B) -> conflict-free ldmatrix.
#define VSA 40
#define VBUF (128 * VSA)          // bf16 elems per operand buffer

__global__ __launch_bounds__(256) void vocab_mma_kernel(
    const float* __restrict__ out_b, float* __restrict__ out)
{
    __shared__ __nv_bfloat16 sA[2][VBUF];
    __shared__ __nv_bfloat16 sB[2][VBUF];

    const int tid  = threadIdx.x;
    const int lane = tid & 31;
    const int wid  = tid >> 5;
    const int wm   = wid & 1;          // 0..1 (64-row half)
    const int wn   = wid >> 1;         // 0..3 (32-col quarter)
    const int tileN = blockIdx.x;
    const int tileM = blockIdx.y;

    const uint32_t sbA = smem_u32(sA);
    const uint32_t sbB = smem_u32(sB);

    // ldmatrix lane address components
    const int rA = lane & 15;                       // A row within 16
    const int kA = (lane >> 4) * 8;                 // A k half
    const int rB = (lane & 7) + ((lane >> 4) << 3); // B n row within 16
    const int kB = ((lane >> 3) & 1) * 8;           // B k half

    const __nv_bfloat16* A2 = g_A2 + (size_t)(tileM * 128) * 1536;

    float acc[4][4][4];
    #pragma unroll
    for (int m = 0; m < 4; m++)
        #pragma unroll
        for (int n = 0; n < 4; n++)
            #pragma unroll
            for (int q = 0; q < 4; q++) acc[m][n][q] = 0.f;

    // global-load indices: 2 uint4 per thread per operand per chunk
    uint4 a_pre[2], b_pre[2];
    #pragma unroll
    for (int i = 0; i < 2; i++) {
        int lin = tid + i * 256;
        int row = lin >> 2, seg = lin & 3;
        a_pre[i] = *(const uint4*)(A2 + (size_t)row * 1536 + seg * 8);
        int n = tileN * 128 + row;
        b_pre[i] = (n < V_) ? *(const uint4*)(g_W2 + (size_t)n * 1536 + seg * 8)
                            : make_uint4(0u, 0u, 0u, 0u);
    }

    int buf = 0;
    for (int k0 = 0; k0 < 1536; k0 += 32) {
        // store prefetched chunk
        #pragma unroll
        for (int i = 0; i < 2; i++) {
            int lin = tid + i * 256;
            int row = lin >> 2, seg = lin & 3;
            *(uint4*)&sA[buf][row * VSA + seg * 8] = a_pre[i];
            *(uint4*)&sB[buf][row * VSA + seg * 8] = b_pre[i];
        }
        __syncthreads();
        // prefetch next chunk
        if (k0 + 32 < 1536) {
            #pragma unroll
            for (int i = 0; i < 2; i++) {
                int lin = tid + i * 256;
                int row = lin >> 2, seg = lin & 3;
                a_pre[i] = *(const uint4*)(A2 + (size_t)row * 1536 + k0 + 32 + seg * 8);
                int n = tileN * 128 + row;
                b_pre[i] = (n < V_) ? *(const uint4*)(g_W2 + (size_t)n * 1536 + k0 + 32 + seg * 8)
                                    : make_uint4(0u, 0u, 0u, 0u);
            }
        }
        // compute 2 x k16 from this buffer
        #pragma unroll
        for (int kk = 0; kk < 32; kk += 16) {
            uint32_t afr[4][4], bfr[2][4];
            #pragma unroll
            for (int mt = 0; mt < 4; mt++) {
                uint32_t ad = sbA + (uint32_t)buf * (VBUF * 2)
                            + ((wm * 64 + mt * 16 + rA) * VSA + kk + kA) * 2;
                ldsm_x4(afr[mt], ad);
            }
            #pragma unroll
            for (int p = 0; p < 2; p++) {
                uint32_t bd = sbB + (uint32_t)buf * (VBUF * 2)
                            + ((wn * 32 + p * 16 + rB) * VSA + kk + kB) * 2;
                ldsm_x4(bfr[p], bd);
            }
            #pragma unroll
            for (int mt = 0; mt < 4; mt++)
                #pragma unroll
                for (int nt = 0; nt < 4; nt++)
                    mma16816(acc[mt][nt], afr[mt], &bfr[nt >> 1][(nt & 1) * 2]);
        }
        __syncthreads();
        buf ^= 1;
    }

    // epilogue: float2 stores (cols are even, contiguous pairs)
    const int rbase = tileM * 128 + wm * 64;
    #pragma unroll
    for (int mt = 0; mt < 4; mt++) {
        int row = rbase + mt * 16 + (lane >> 2);
        #pragma unroll
        for (int nt = 0; nt < 4; nt++) {
            int col = tileN * 128 + wn * 32 + nt * 8 + (lane & 3) * 2;
            if (col < V_) {
                float b0 = out_b[col], b1 = out_b[col + 1];
                float2 v0 = make_float2(acc[mt][nt][0] + b0, acc[mt][nt][1] + b1);
                float2 v1 = make_float2(acc[mt][nt][2] + b0, acc[mt][nt][3] + b1);
                *(float2*)&out[(size_t)row * V_ + col] = v0;
                *(float2*)&out[(size_t)(row + 8) * V_ + col] = v1;
            }
        }
    }
}

// ---------------- build bf16-split operands ------------------------------
__global__ void build_A2_kernel()
{
    int idx = blockIdx.x * blockDim.x + threadIdx.x;    // 8192*512
    int r = idx >> 9, k = idx & 511;
    float a = g_hs[idx];
    __nv_bfloat16 hi = __float2bfloat16_rn(a);
    __nv_bfloat16 lo = __float2bfloat16_rn(a - __bfloat162float(hi));
    size_t base = (size_t)r * 1536 + k;
    g_A2[base]        = hi;
    g_A2[base + 512]  = hi;
    g_A2[base + 1024] = lo;
}

__global__ void build_W2_kernel(const float* __restrict__ out_W)
{
    int idx = blockIdx.x * blockDim.x + threadIdx.x;    // 10000*512
    if (idx >= V_ * 512) return;
    int n = idx >> 9, k = idx & 511;
    float w = out_W[idx];
    __nv_bfloat16 hi = __float2bfloat16_rn(w);
    __nv_bfloat16 lo = __float2bfloat16_rn(w - __bfloat162float(hi));
    size_t base = (size_t)n * 1536 + k;
    g_W2[base]        = hi;
    g_W2[base + 512]  = lo;
    g_W2[base + 1024] = hi;
}

// ---------------- double-buffered 16x64 tile GEMM (K mult of 16) ---------
__device__ __forceinline__ void tile_gemm16_db(
    const float* __restrict__ A, int lda,
    const float* __restrict__ W, int ldw,
    const float* __restrict__ bias,
    const float* __restrict__ D, int ldd,
    float* __restrict__ C, int ldc,
    int K, int rowBase, int colBase,
    float (&As)[2][16][20], float (&Ws)[2][16][68])
{
    const int tid = threadIdx.x;
    const int tx = tid & 15;
    const int ty = tid >> 4;
    const int lr = tid >> 4;
    const int lc = tid & 15;

    float acc[4] = {0.f, 0.f, 0.f, 0.f};

    float a_pre = A[(size_t)(rowBase + lr) * lda + lc];
    float w_pre[4];
    #pragma unroll
    for (int i = 0; i < 4; i++) {
        int r = (tid + i * 256) >> 4;
        w_pre[i] = W[(size_t)(colBase + r) * ldw + lc];
    }

    int buf = 0;
    for (int k0 = 0; k0 < K; k0 += 16) {
        As[buf][lc][lr] = a_pre;
        #pragma unroll
        for (int i = 0; i < 4; i++) {
            int r = (tid + i * 256) >> 4;
            Ws[buf][lc][r] = w_pre[i];
        }
        __syncthreads();
        if (k0 + 16 < K) {
            a_pre = A[(size_t)(rowBase + lr) * lda + k0 + 16 + lc];
            #pragma unroll
            for (int i = 0; i < 4; i++) {
                int r = (tid + i * 256) >> 4;
                w_pre[i] = W[(size_t)(colBase + r) * ldw + k0 + 16 + lc];
            }
        }
        #pragma unroll
        for (int kk = 0; kk < 16; kk++) {
            float a = As[buf][kk][ty];
            float w0 = Ws[buf][kk][tx * 4 + 0];
            float w1 = Ws[buf][kk][tx * 4 + 1];
            float w2 = Ws[buf][kk][tx * 4 + 2];
            float w3 = Ws[buf][kk][tx * 4 + 3];
            acc[0] += a * w0; acc[1] += a * w1;
            acc[2] += a * w2; acc[3] += a * w3;
        }
        buf ^= 1;
    }

    int r = rowBase + ty;
    #pragma unroll
    for (int j = 0; j < 4; j++) {
        int c = colBase + tx * 4 + j;
        float v = acc[j];
        if (bias) v += bias[c];
        if (D)    v += D[(size_t)r * ldd + c];
        C[(size_t)r * ldc + c] = v;
    }
}

__device__ __forceinline__ float sigmoidf_(float x) { return 1.0f / (1.0f + expf(-x)); }

// ---------------- persistent recurrence kernel: 256 blocks x 256 thr -----
__global__ __launch_bounds__(256, 2) void recurrence_kernel(
    const float* __restrict__ combWa,
    const float* __restrict__ Wih,
    const float* __restrict__ bih,
    const float* __restrict__ bhh)
{
    __shared__ float As[2][16][20];
    __shared__ float Ws[2][16][68];
    __shared__ float red[256];
    const int bid = blockIdx.x;
    const int tid = threadIdx.x;

    for (int t = 0; t < T_; t++) {
        {
            int tm = bid >> 5, tn = bid & 31;
            tile_gemm16_db(g_h, H_, g_Whcat, H_, nullptr, nullptr, 0,
                           g_hproj, 2048, H_, tm * 16, tn * 64, As, Ws);
        }
        grid_barrier();

        if (bid < B_) {
            const int b = bid;
            const float* ax = g_AX + ((size_t)t * B_ + b) * H_;
            const float* hp = g_hproj + (size_t)b * 2048;
            float v0 = ax[tid]       + hp[tid];
            float v1 = ax[tid + 256] + hp[tid + 256];
            red[tid] = fmaxf(v0, v1);
            __syncthreads();
            for (int s = 128; s > 0; s >>= 1) {
                if (tid < s) red[tid] = fmaxf(red[tid], red[tid + s]);
                __syncthreads();
            }
            float mx = red[0];
            __syncthreads();
            float e0 = expf(v0 - mx), e1 = expf(v1 - mx);
            red[tid] = e0 + e1;
            __syncthreads();
            for (int s = 128; s > 0; s >>= 1) {
                if (tid < s) red[tid] += red[tid + s];
                __syncthreads();
            }
            float inv = 1.0f / red[0];
            __syncthreads();
            g_applied[b * E_ + tid]       = g_feats[b * E_ + tid]       * (e0 * inv);
            g_applied[b * E_ + tid + 256] = g_feats[b * E_ + tid + 256] * (e1 * inv);
        }
        grid_barrier();

        if (bid < 64) {
            int tm = bid >> 3, tn = bid & 7;
            tile_gemm16_db(g_applied, E_, combWa, 1024, nullptr,
                           g_CX + (size_t)t * B_ * H_, H_,
                           g_inp, H_, E_, tm * 16, tn * 64, As, Ws);
        }
        grid_barrier();

        if (bid < 192) {
            int tm = bid / 24, tn = bid % 24;
            tile_gemm16_db(g_inp, H_, Wih, H_, bih, nullptr, 0,
                           g_gx, 1536, H_, tm * 16, tn * 64, As, Ws);
        }
        grid_barrier();

        if (bid < B_) {
            const int b = bid;
            const float* gx = g_gx + (size_t)b * 1536;
            const float* hp = g_hproj + (size_t)b * 2048 + 512;
            #pragma unroll
            for (int u = 0; u < 2; u++) {
                int j = tid + u * 256;
                float r = sigmoidf_(gx[j]        + hp[j]        + bhh[j]);
                float z = sigmoidf_(gx[512 + j]  + hp[512 + j]  + bhh[512 + j]);
                float n = tanhf(gx[1024 + j] + r * (hp[1024 + j] + bhh[1024 + j]));
                float hprev = g_h[b * H_ + j];
                float h = (1.0f - z) * n + z * hprev;
                g_h[b * H_ + j] = h;
                g_hs[(size_t)t * B_ * H_ + b * H_ + j] = h;
            }
        }
        grid_barrier();
    }
}

// ---------------- generic SGEMM (small shapes) ---------------------------
#define BM 64
#define BN 64
#define BK 16

__global__ __launch_bounds__(256) void sgemm2(
    const float* __restrict__ A, int lda,
    const float* __restrict__ W, int ldw,
    const float* __restrict__ bias,
    const float* __restrict__ D, int ldd,
    float* __restrict__ C, int ldc,
    int M, int N, int K)
{
    __shared__ float As[BK][BM + 1];
    __shared__ float Ws[BK][BN + 1];

    const int tid = threadIdx.x;
    const int tx = tid & 15;
    const int ty = tid >> 4;
    const int rowBase = blockIdx.y * BM;
    const int colBase = blockIdx.x * BN;

    float acc[4][4] = {};

    for (int k0 = 0; k0 < K; k0 += BK) {
        #pragma unroll
        for (int i = 0; i < 4; i++) {
            int lin = tid + i * 256;
            int r = lin >> 4;
            int c = lin & 15;
            int ar = rowBase + r;
            As[c][r] = (ar < M) ? A[(size_t)ar * lda + k0 + c] : 0.f;
            int wr = colBase + r;
            Ws[c][r] = (wr < N) ? W[(size_t)wr * ldw + k0 + c] : 0.f;
        }
        __syncthreads();
        #pragma unroll
        for (int kk = 0; kk < BK; kk++) {
            float a[4], w[4];
            #pragma unroll
            for (int i = 0; i < 4; i++) a[i] = As[kk][ty * 4 + i];
            #pragma unroll
            for (int j = 0; j < 4; j++) w[j] = Ws[kk][tx * 4 + j];
            #pragma unroll
            for (int i = 0; i < 4; i++)
                #pragma unroll
                for (int j = 0; j < 4; j++)
                    acc[i][j] += a[i] * w[j];
        }
        __syncthreads();
    }

    #pragma unroll
    for (int i = 0; i < 4; i++) {
        int r = rowBase + ty * 4 + i;
        if (r >= M) continue;
        #pragma unroll
        for (int j = 0; j < 4; j++) {
            int c = colBase + tx * 4 + j;
            if (c < N) {
                float v = acc[i][j];
                if (bias) v += bias[c];
                if (D)    v += D[(size_t)r * ldd + c];
                C[(size_t)r * ldc + c] = v;
            }
        }
    }
}

// ---------------- big SGEMM: BM=128, BN=64, 8x4 micro, double-buffered ---
#define GBM 128
#define GBN 64

__global__ __launch_bounds__(256) void sgemm_big(
    const float* __restrict__ A, int lda,
    const float* __restrict__ W, int ldw,
    const float* __restrict__ bias,
    float* __restrict__ C, int ldc,
    int M, int N, int K)
{
    __shared__ float As[2][16][GBM + 4];
    __shared__ float Ws[2][16][GBN + 4];

    const int tid = threadIdx.x;
    const int tx = tid & 15;
    const int ty = tid >> 4;
    const int rowBase = blockIdx.y * GBM;
    const int colBase = blockIdx.x * GBN;
    const int lc = tid & 15;

    float acc[8][4] = {};

    float a_pre[8], w_pre[4];
    #pragma unroll
    for (int i = 0; i < 8; i++) {
        int r = (tid + i * 256) >> 4;
        a_pre[i] = A[(size_t)(rowBase + r) * lda + lc];
    }
    #pragma unroll
    for (int i = 0; i < 4; i++) {
        int r = (tid + i * 256) >> 4;
        int wr = colBase + r;
        w_pre[i] = (wr < N) ? W[(size_t)wr * ldw + lc] : 0.f;
    }

    int buf = 0;
    for (int k0 = 0; k0 < K; k0 += 16) {
        #pragma unroll
        for (int i = 0; i < 8; i++) {
            int r = (tid + i * 256) >> 4;
            As[buf][lc][r] = a_pre[i];
        }
        #pragma unroll
        for (int i = 0; i < 4; i++) {
            int r = (tid + i * 256) >> 4;
            Ws[buf][lc][r] = w_pre[i];
        }
        __syncthreads();
        if (k0 + 16 < K) {
            #pragma unroll
            for (int i = 0; i < 8; i++) {
                int r = (tid + i * 256) >> 4;
                a_pre[i] = A[(size_t)(rowBase + r) * lda + k0 + 16 + lc];
            }
            #pragma unroll
            for (int i = 0; i < 4; i++) {
                int r = (tid + i * 256) >> 4;
                int wr = colBase + r;
                w_pre[i] = (wr < N) ? W[(size_t)wr * ldw + k0 + 16 + lc] : 0.f;
            }
        }
        #pragma unroll
        for (int kk = 0; kk < 16; kk++) {
            float a[8], w[4];
            #pragma unroll
            for (int j = 0; j < 4; j++) w[j] = Ws[buf][kk][tx * 4 + j];
            #pragma unroll
            for (int i = 0; i < 8; i++) a[i] = As[buf][kk][ty * 8 + i];
            #pragma unroll
            for (int i = 0; i < 8; i++)
                #pragma unroll
                for (int j = 0; j < 4; j++)
                    acc[i][j] += a[i] * w[j];
        }
        buf ^= 1;
    }

    #pragma unroll
    for (int i = 0; i < 8; i++) {
        int r = rowBase + ty * 8 + i;
        #pragma unroll
        for (int j = 0; j < 4; j++) {
            int c = colBase + tx * 4 + j;
            if (c < N) {
                float v = acc[i][j];
                if (bias) v += bias[c];
                C[(size_t)r * ldc + c] = v;
            }
        }
    }
}

// ---------------- BatchNorm1d (training mode) ----------------------------
__global__ void bn_kernel(const float* __restrict__ gamma, const float* __restrict__ beta)
{
    int e = blockIdx.x;
    int b = threadIdx.x;
    float v = g_f[b * E_ + e];
    __shared__ float red[B_];
    __shared__ float mu_s, var_s;

    red[b] = v;
    __syncthreads();
    for (int s = B_ / 2; s > 0; s >>= 1) {
        if (b < s) red[b] += red[b + s];
        __syncthreads();
    }
    if (b == 0) mu_s = red[0] * (1.0f / B_);
    __syncthreads();
    float d = v - mu_s;
    red[b] = d * d;
    __syncthreads();
    for (int s = B_ / 2; s > 0; s >>= 1) {
        if (b < s) red[b] += red[b + s];
        __syncthreads();
    }
    if (b == 0) var_s = red[0] * (1.0f / B_);
    __syncthreads();
    g_feats[b * E_ + e] = gamma[e] * d * rsqrtf(var_s + 1e-5f) + beta[e];
}

// ---------------- build X for all steps ----------------------------------
__global__ void build_X_kernel(const float* __restrict__ embed_W,
                               const int* __restrict__ captions)
{
    int idx = blockIdx.x * blockDim.x + threadIdx.x;
    int t = idx >> 16;
    int rem = idx & 65535;
    int b = rem >> 9;
    int e = rem & 511;
    float v;
    if (t == 0) v = g_feats[b * E_ + e];
    else        v = embed_W[(size_t)captions[b * T_ + (t - 1)] * E_ + e];
    g_X[idx] = v;
}

// ---------------- build [attn_Wh ; gru_Whh] ------------------------------
__global__ void build_Whcat_kernel(const float* __restrict__ attn_W,
                                   const float* __restrict__ gru_Whh)
{
    int idx = blockIdx.x * blockDim.x + threadIdx.x;
    int n = idx >> 9;
    int k = idx & 511;
    float v;
    if (n < 512) v = attn_W[(size_t)n * 1024 + 512 + k];
    else         v = gru_Whh[(size_t)(n - 512) * 512 + k];
    g_Whcat[idx] = v;
}

// ---------------- log_softmax ---------------------------------------------
__global__ void logsoftmax_kernel(float* __restrict__ out)
{
    extern __shared__ float row[];
    __shared__ float red[256];
    __shared__ float mx_s, lse_s;
    int r = blockIdx.x;
    int tid = threadIdx.x;
    float* p = out + (size_t)r * V_;

    float mx = -3.4e38f;
    for (int i = tid; i < V_; i += 256) {
        float v = p[i];
        row[i] = v;
        mx = fmaxf(mx, v);
    }
    red[tid] = mx;
    __syncthreads();
    for (int s = 128; s > 0; s >>= 1) {
        if (tid < s) red[tid] = fmaxf(red[tid], red[tid + s]);
        __syncthreads();
    }
    if (tid == 0) mx_s = red[0];
    __syncthreads();

    float sum = 0.f;
    for (int i = tid; i < V_; i += 256) sum += expf(row[i] - mx_s);
    red[tid] = sum;
    __syncthreads();
    for (int s = 128; s > 0; s >>= 1) {
        if (tid < s) red[tid] += red[tid + s];
        __syncthreads();
    }
    if (tid == 0) lse_s = mx_s + logf(red[0]);
    __syncthreads();

    for (int i = tid; i < V_; i += 256) p[i] = row[i] - lse_s;
}

// ---------------- transpose hs [T,B,H] -> [B,T,H] ------------------------
__global__ void transpose_h_kernel(float* __restrict__ out2)
{
    int idx = blockIdx.x * blockDim.x + threadIdx.x;
    int j = idx & 511;
    int b = (idx >> 9) & 127;
    int t = idx >> 16;
    out2[((size_t)b * T_ + t) * H_ + j] = g_hs[idx];
}

// ---------------- host launch ---------------------------------------------
extern "C" void kernel_launch(void* const* d_in, const int* in_sizes, int n_in,
                              void* d_out, int out_size)
{
    const float* features = (const float*)d_in[0];
    const int*   captions = (const int*)d_in[1];
    const float* h0       = (const float*)d_in[2];
    const float* embed_W  = (const float*)d_in[4];
    const float* fc_W     = (const float*)d_in[5];
    const float* fc_b     = (const float*)d_in[6];
    const float* bn_gamma = (const float*)d_in[7];
    const float* bn_beta  = (const float*)d_in[8];
    const float* attn_W   = (const float*)d_in[9];
    const float* attn_b   = (const float*)d_in[10];
    const float* comb_W   = (const float*)d_in[11];
    const float* comb_b   = (const float*)d_in[12];
    const float* gru_Wih  = (const float*)d_in[13];
    const float* gru_Whh  = (const float*)d_in[14];
    const float* gru_bih  = (const float*)d_in[15];
    const float* gru_bhh  = (const float*)d_in[16];
    const float* out_W    = (const float*)d_in[17];
    const float* out_b    = (const float*)d_in[18];
    float* out = (float*)d_out;

    float *p_f, *p_h, *p_X, *p_AX, *p_CX, *p_hs;
    cudaGetSymbolAddress((void**)&p_f,  g_f);
    cudaGetSymbolAddress((void**)&p_h,  g_h);
    cudaGetSymbolAddress((void**)&p_X,  g_X);
    cudaGetSymbolAddress((void**)&p_AX, g_AX);
    cudaGetSymbolAddress((void**)&p_CX, g_CX);
    cudaGetSymbolAddress((void**)&p_hs, g_hs);

    cudaMemcpyAsync(p_h, h0, (size_t)B_ * H_ * sizeof(float), cudaMemcpyDeviceToDevice);

    dim3 blk(256);

    // fc + batchnorm
    sgemm2<<<dim3(E_ / 64, B_ / 64), blk>>>(features, FIN_, fc_W, FIN_, fc_b,
                                            nullptr, 0, p_f, E_, B_, E_, FIN_);
    bn_kernel<<<E_, B_>>>(bn_gamma, bn_beta);

    // hoisted x-dependent work
    build_X_kernel<<<(T_ * B_ * E_) / 256, 256>>>(embed_W, captions);
    build_Whcat_kernel<<<(2048 * H_) / 256, 256>>>(attn_W, gru_Whh);
    build_W2_kernel<<<(V_ * 512 + 255) / 256, 256>>>(out_W);
    sgemm_big<<<dim3(H_ / GBN, (T_ * B_) / GBM), blk>>>(p_X, E_, attn_W, 1024, attn_b,
                                                        p_AX, H_, T_ * B_, H_, E_);
    sgemm_big<<<dim3(H_ / GBN, (T_ * B_) / GBM), blk>>>(p_X, E_, comb_W, 1024, comb_b,
                                                        p_CX, H_, T_ * B_, H_, E_);

    // fused persistent recurrence: ONE launch, 256 co-resident blocks
    recurrence_kernel<<<NBLK, 256>>>(comb_W + 512, gru_Wih, gru_bih, gru_bhh);

    // vocab projection on HMMA tensor cores (bf16 3-term split)
    build_A2_kernel<<<(T_ * B_ * 512) / 256, 256>>>();
    vocab_mma_kernel<<<dim3((V_ + 127) / 128, (T_ * B_) / 128), blk>>>(out_b, out);
    logsoftmax_kernel<<<T_ * B_, 256, V_ * sizeof(float)>>>(out);

    transpose_h_kernel<<<(T_ * B_ * H_) / 256, 256>>>(out + (size_t)T_ * B_ * V_);
}

// round 15
// speedup vs baseline: 3.5781x; 1.1680x over previous
#include <cuda_runtime.h>
#include <cuda_bf16.h>
#include <math.h>
#include <stdint.h>

#define B_   128
#define T_   64
#define E_   512
#define H_   512
#define V_   10000
#define FIN_ 2048
#define NBLK 256

// ---------------- scratch (device globals; no allocation) ----------------
__device__ float g_f[B_ * E_];
__device__ float g_feats[B_ * E_];
__device__ float g_h[B_ * H_];
__device__ float g_X[T_ * B_ * E_];
__device__ float g_AX[T_ * B_ * H_];
__device__ float g_CX[T_ * B_ * H_];
__device__ float g_hproj[B_ * 2048];
__device__ float g_gx[B_ * 3 * H_];
__device__ float g_hs[T_ * B_ * H_];

// bf16-split operands (K' = 3*512 = 1536)
__device__ __nv_bfloat16 g_A2[(size_t)T_ * B_ * 1536];     // vocab A (A-side)
__device__ __nv_bfloat16 g_W2[(size_t)V_ * 1536];          // vocab W (B-side)
__device__ __nv_bfloat16 g_Whcat2[2048 * 1536];            // B-side
__device__ __nv_bfloat16 g_combWa2[512 * 1536];            // B-side
__device__ __nv_bfloat16 g_Wih2[1536 * 1536];              // B-side
__device__ __nv_bfloat16 g_h2[B_ * 1536];                  // A-side
__device__ __nv_bfloat16 g_applied2[B_ * 1536];            // A-side
__device__ __nv_bfloat16 g_inp2[B_ * 1536];                // A-side

// barrier state on separate 256B lines
__device__ __align__(256) unsigned int g_bar_count[64];
__device__ __align__(256) unsigned int g_bar_release[64];

// ---------------- software grid barrier (all NBLK blocks resident) -------
__device__ __forceinline__ void grid_barrier()
{
    __syncthreads();
    if (threadIdx.x == 0) {
        volatile unsigned int* rel = g_bar_release;
        unsigned int before = rel[0];
        __threadfence();
        unsigned int t = atomicAdd(&g_bar_count[0], 1u);
        if (t == NBLK - 1) {
            atomicExch(&g_bar_count[0], 0u);
            __threadfence();
            atomicAdd(&g_bar_release[0], 1u);
        } else {
            while (rel[0] == before) { }
        }
        __threadfence();
    }
    __syncthreads();
}

// ================= baseline-PTX tensor helpers (sm_80+) ==================
__device__ __forceinline__ uint32_t smem_u32(const void* p) {
    uint32_t a;
    asm("{ .reg .u64 t; cvta.to.shared.u64 t, %1; cvt.u32.u64 %0, t; }"
        : "=r"(a) : "l"(p));
    return a;
}
__device__ __forceinline__ void ldsm_x4(uint32_t* r, uint32_t addr) {
    asm volatile("ldmatrix.sync.aligned.m8n8.x4.shared.b16 {%0,%1,%2,%3}, [%4];"
                 : "=r"(r[0]), "=r"(r[1]), "=r"(r[2]), "=r"(r[3]) : "r"(addr));
}
__device__ __forceinline__ void ldsm_x2(uint32_t* r, uint32_t addr) {
    asm volatile("ldmatrix.sync.aligned.m8n8.x2.shared.b16 {%0,%1}, [%2];"
                 : "=r"(r[0]), "=r"(r[1]) : "r"(addr));
}
__device__ __forceinline__ void mma16816(float* c, const uint32_t* a, const uint32_t* b) {
    asm volatile(
        "mma.sync.aligned.m16n8k16.row.col.f32.bf16.bf16.f32 "
        "{%0,%1,%2,%3}, {%4,%5,%6,%7}, {%8,%9}, {%0,%1,%2,%3};"
        : "+f"(c[0]), "+f"(c[1]), "+f"(c[2]), "+f"(c[3])
        : "r"(a[0]), "r"(a[1]), "r"(a[2]), "r"(a[3]), "r"(b[0]), "r"(b[1]));
}

__device__ __forceinline__ void split3(float v, __nv_bfloat16& hi, __nv_bfloat16& lo) {
    hi = __float2bfloat16_rn(v);
    lo = __float2bfloat16_rn(v - __bfloat162float(hi));
}

// ---------------- vocab mma.sync GEMM: out = A2 @ W2^T + out_b -----------
#define VSA 40
#define VBUF (128 * VSA)

__global__ __launch_bounds__(256) void vocab_mma_kernel(
    const float* __restrict__ out_b, float* __restrict__ out)
{
    __shared__ __nv_bfloat16 sA[2][VBUF];
    __shared__ __nv_bfloat16 sB[2][VBUF];

    const int tid  = threadIdx.x;
    const int lane = tid & 31;
    const int wid  = tid >> 5;
    const int wm   = wid & 1;
    const int wn   = wid >> 1;
    const int tileN = blockIdx.x;
    const int tileM = blockIdx.y;

    const uint32_t sbA = smem_u32(sA);
    const uint32_t sbB = smem_u32(sB);

    const int rA = lane & 15;
    const int kA = (lane >> 4) * 8;
    const int rB = (lane & 7) + ((lane >> 4) << 3);
    const int kB = ((lane >> 3) & 1) * 8;

    const __nv_bfloat16* A2 = g_A2 + (size_t)(tileM * 128) * 1536;

    float acc[4][4][4];
    #pragma unroll
    for (int m = 0; m < 4; m++)
        #pragma unroll
        for (int n = 0; n < 4; n++)
            #pragma unroll
            for (int q = 0; q < 4; q++) acc[m][n][q] = 0.f;

    uint4 a_pre[2], b_pre[2];
    #pragma unroll
    for (int i = 0; i < 2; i++) {
        int lin = tid + i * 256;
        int row = lin >> 2, seg = lin & 3;
        a_pre[i] = *(const uint4*)(A2 + (size_t)row * 1536 + seg * 8);
        int n = tileN * 128 + row;
        b_pre[i] = (n < V_) ? *(const uint4*)(g_W2 + (size_t)n * 1536 + seg * 8)
                            : make_uint4(0u, 0u, 0u, 0u);
    }

    int buf = 0;
    for (int k0 = 0; k0 < 1536; k0 += 32) {
        #pragma unroll
        for (int i = 0; i < 2; i++) {
            int lin = tid + i * 256;
            int row = lin >> 2, seg = lin & 3;
            *(uint4*)&sA[buf][row * VSA + seg * 8] = a_pre[i];
            *(uint4*)&sB[buf][row * VSA + seg * 8] = b_pre[i];
        }
        __syncthreads();
        if (k0 + 32 < 1536) {
            #pragma unroll
            for (int i = 0; i < 2; i++) {
                int lin = tid + i * 256;
                int row = lin >> 2, seg = lin & 3;
                a_pre[i] = *(const uint4*)(A2 + (size_t)row * 1536 + k0 + 32 + seg * 8);
                int n = tileN * 128 + row;
                b_pre[i] = (n < V_) ? *(const uint4*)(g_W2 + (size_t)n * 1536 + k0 + 32 + seg * 8)
                                    : make_uint4(0u, 0u, 0u, 0u);
            }
        }
        #pragma unroll
        for (int kk = 0; kk < 32; kk += 16) {
            uint32_t afr[4][4], bfr[2][4];
            #pragma unroll
            for (int mt = 0; mt < 4; mt++) {
                uint32_t ad = sbA + (uint32_t)buf * (VBUF * 2)
                            + ((wm * 64 + mt * 16 + rA) * VSA + kk + kA) * 2;
                ldsm_x4(afr[mt], ad);
            }
            #pragma unroll
            for (int p = 0; p < 2; p++) {
                uint32_t bd = sbB + (uint32_t)buf * (VBUF * 2)
                            + ((wn * 32 + p * 16 + rB) * VSA + kk + kB) * 2;
                ldsm_x4(bfr[p], bd);
            }
            #pragma unroll
            for (int mt = 0; mt < 4; mt++)
                #pragma unroll
                for (int nt = 0; nt < 4; nt++)
                    mma16816(acc[mt][nt], afr[mt], &bfr[nt >> 1][(nt & 1) * 2]);
        }
        __syncthreads();
        buf ^= 1;
    }

    const int rbase = tileM * 128 + wm * 64;
    #pragma unroll
    for (int mt = 0; mt < 4; mt++) {
        int row = rbase + mt * 16 + (lane >> 2);
        #pragma unroll
        for (int nt = 0; nt < 4; nt++) {
            int col = tileN * 128 + wn * 32 + nt * 8 + (lane & 3) * 2;
            if (col < V_) {
                float b0 = out_b[col], b1 = out_b[col + 1];
                float2 v0 = make_float2(acc[mt][nt][0] + b0, acc[mt][nt][1] + b1);
                float2 v1 = make_float2(acc[mt][nt][2] + b0, acc[mt][nt][3] + b1);
                *(float2*)&out[(size_t)row * V_ + col] = v0;
                *(float2*)&out[(size_t)(row + 8) * V_ + col] = v1;
            }
        }
    }
}

// ---------------- 16x64 mma tile for the recurrence ----------------------
// 256 thr, 8 warps, warp w -> n8 strip at colBase + w*8. K'=1536, k32 chunks.
__device__ __forceinline__ void mma_tile16x64(
    const __nv_bfloat16* __restrict__ A2, int rowBase,
    const __nv_bfloat16* __restrict__ W2, int colBase,
    const float* __restrict__ bias,
    const float* __restrict__ Dres, int ldd,
    float* __restrict__ Cf, int ldcf,
    __nv_bfloat16* __restrict__ C2,
    __nv_bfloat16 (&sA)[2][640], __nv_bfloat16 (&sB)[2][2560])
{
    const int tid = threadIdx.x, lane = tid & 31, w = tid >> 5;
    const uint32_t baA = smem_u32(sA), baB = smem_u32(sB);
    const int brow = tid >> 2, bseg = tid & 3;     // B: 256 threads x uint4
    const int rA = lane & 15, kA = (lane >> 4) * 8;
    const int rBl = lane & 7, kBl = ((lane >> 3) & 1) * 8;

    float acc[4] = {0.f, 0.f, 0.f, 0.f};

    uint4 bpre, apre;
    bpre = *(const uint4*)(W2 + (size_t)(colBase + brow) * 1536 + bseg * 8);
    if (tid < 64)
        apre = *(const uint4*)(A2 + (size_t)(rowBase + brow) * 1536 + bseg * 8);

    int buf = 0;
    for (int k0 = 0; k0 < 1536; k0 += 32) {
        *(uint4*)&sB[buf][brow * 40 + bseg * 8] = bpre;
        if (tid < 64) *(uint4*)&sA[buf][brow * 40 + bseg * 8] = apre;
        __syncthreads();
        if (k0 + 32 < 1536) {
            bpre = *(const uint4*)(W2 + (size_t)(colBase + brow) * 1536 + k0 + 32 + bseg * 8);
            if (tid < 64)
                apre = *(const uint4*)(A2 + (size_t)(rowBase + brow) * 1536 + k0 + 32 + bseg * 8);
        }
        uint32_t offA = baA + (uint32_t)buf * (640 * 2);
        uint32_t offB = baB + (uint32_t)buf * (2560 * 2);
        #pragma unroll
        for (int kk = 0; kk < 32; kk += 16) {
            uint32_t afr[4], bfr[2];
            ldsm_x4(afr, offA + (uint32_t)((rA * 40 + kk + kA) * 2));
            ldsm_x2(bfr, offB + (uint32_t)(((w * 8 + rBl) * 40 + kk + kBl) * 2));
            mma16816(acc, afr, bfr);
        }
        buf ^= 1;
    }

    const int row0 = rowBase + (lane >> 2);
    const int colg = colBase + w * 8 + (lane & 3) * 2;
    float b0 = bias ? bias[colg] : 0.f;
    float b1 = bias ? bias[colg + 1] : 0.f;
    float v00 = acc[0] + b0, v01 = acc[1] + b1;
    float v10 = acc[2] + b0, v11 = acc[3] + b1;
    if (Dres) {
        v00 += Dres[(size_t)row0 * ldd + colg];
        v01 += Dres[(size_t)row0 * ldd + colg + 1];
        v10 += Dres[(size_t)(row0 + 8) * ldd + colg];
        v11 += Dres[(size_t)(row0 + 8) * ldd + colg + 1];
    }
    if (Cf) {
        Cf[(size_t)row0 * ldcf + colg]           = v00;
        Cf[(size_t)row0 * ldcf + colg + 1]       = v01;
        Cf[(size_t)(row0 + 8) * ldcf + colg]     = v10;
        Cf[(size_t)(row0 + 8) * ldcf + colg + 1] = v11;
    }
    if (C2) {
        __nv_bfloat16 hi, lo;
        split3(v00, hi, lo);
        C2[(size_t)row0 * 1536 + colg] = hi;
        C2[(size_t)row0 * 1536 + colg + 512] = hi;
        C2[(size_t)row0 * 1536 + colg + 1024] = lo;
        split3(v01, hi, lo);
        C2[(size_t)row0 * 1536 + colg + 1] = hi;
        C2[(size_t)row0 * 1536 + colg + 513] = hi;
        C2[(size_t)row0 * 1536 + colg + 1025] = lo;
        split3(v10, hi, lo);
        C2[(size_t)(row0 + 8) * 1536 + colg] = hi;
        C2[(size_t)(row0 + 8) * 1536 + colg + 512] = hi;
        C2[(size_t)(row0 + 8) * 1536 + colg + 1024] = lo;
        split3(v11, hi, lo);
        C2[(size_t)(row0 + 8) * 1536 + colg + 1] = hi;
        C2[(size_t)(row0 + 8) * 1536 + colg + 513] = hi;
        C2[(size_t)(row0 + 8) * 1536 + colg + 1025] = lo;
    }
}

__device__ __forceinline__ float sigmoidf_(float x) { return 1.0f / (1.0f + expf(-x)); }

// ---------------- persistent recurrence kernel (HMMA GEMMs) --------------
__global__ __launch_bounds__(256, 2) void recurrence_kernel(
    const float* __restrict__ bih,
    const float* __restrict__ bhh)
{
    __shared__ __nv_bfloat16 sA[2][640];
    __shared__ __nv_bfloat16 sB[2][2560];
    __shared__ float red[256];
    const int bid = blockIdx.x;
    const int tid = threadIdx.x;

    for (int t = 0; t < T_; t++) {
        // P1: hproj[128,2048] = h2 @ Whcat2^T ; 8x32 = 256 tiles of 16x64
        {
            int tm = bid >> 5, tn = bid & 31;
            mma_tile16x64(g_h2, tm * 16, g_Whcat2, tn * 64,
                          nullptr, nullptr, 0, g_hproj, 2048, nullptr, sA, sB);
        }
        grid_barrier();

        // P2: softmax(AX[t]+hproj[:, :512]) -> applied2 (triple)
        if (bid < B_) {
            const int b = bid;
            const float* ax = g_AX + ((size_t)t * B_ + b) * H_;
            const float* hp = g_hproj + (size_t)b * 2048;
            float v0 = ax[tid]       + hp[tid];
            float v1 = ax[tid + 256] + hp[tid + 256];
            red[tid] = fmaxf(v0, v1);
            __syncthreads();
            for (int s = 128; s > 0; s >>= 1) {
                if (tid < s) red[tid] = fmaxf(red[tid], red[tid + s]);
                __syncthreads();
            }
            float mx = red[0];
            __syncthreads();
            float e0 = expf(v0 - mx), e1 = expf(v1 - mx);
            red[tid] = e0 + e1;
            __syncthreads();
            for (int s = 128; s > 0; s >>= 1) {
                if (tid < s) red[tid] += red[tid + s];
                __syncthreads();
            }
            float inv = 1.0f / red[0];
            __syncthreads();
            float a0 = g_feats[b * E_ + tid]       * (e0 * inv);
            float a1 = g_feats[b * E_ + tid + 256] * (e1 * inv);
            __nv_bfloat16 hi, lo;
            split3(a0, hi, lo);
            g_applied2[(size_t)b * 1536 + tid] = hi;
            g_applied2[(size_t)b * 1536 + tid + 512] = hi;
            g_applied2[(size_t)b * 1536 + tid + 1024] = lo;
            split3(a1, hi, lo);
            g_applied2[(size_t)b * 1536 + tid + 256] = hi;
            g_applied2[(size_t)b * 1536 + tid + 768] = hi;
            g_applied2[(size_t)b * 1536 + tid + 1280] = lo;
        }
        grid_barrier();

        // P3: inp2 = split(CX[t] + applied2 @ combWa2^T) ; 8x8 = 64 tiles
        if (bid < 64) {
            int tm = bid >> 3, tn = bid & 7;
            mma_tile16x64(g_applied2, tm * 16, g_combWa2, tn * 64,
                          nullptr, g_CX + (size_t)t * B_ * H_, H_,
                          nullptr, 0, g_inp2, sA, sB);
        }
        grid_barrier();

        // P4: gx[128,1536] = inp2 @ Wih2^T + bih ; 8x24 = 192 tiles
        if (bid < 192) {
            int tm = bid / 24, tn = bid % 24;
            mma_tile16x64(g_inp2, tm * 16, g_Wih2, tn * 64,
                          bih, nullptr, 0, g_gx, 1536, nullptr, sA, sB);
        }
        grid_barrier();

        // P5: GRU gates -> g_h (fp32), g_hs, g_h2 (triple), g_A2 row (triple)
        if (bid < B_) {
            const int b = bid;
            const float* gx = g_gx + (size_t)b * 1536;
            const float* hp = g_hproj + (size_t)b * 2048 + 512;
            #pragma unroll
            for (int u = 0; u < 2; u++) {
                int j = tid + u * 256;
                float r = sigmoidf_(gx[j]        + hp[j]        + bhh[j]);
                float z = sigmoidf_(gx[512 + j]  + hp[512 + j]  + bhh[512 + j]);
                float n = tanhf(gx[1024 + j] + r * (hp[1024 + j] + bhh[1024 + j]));
                float hprev = g_h[b * H_ + j];
                float h = (1.0f - z) * n + z * hprev;
                g_h[b * H_ + j] = h;
                g_hs[(size_t)t * B_ * H_ + b * H_ + j] = h;
                __nv_bfloat16 hi, lo;
                split3(h, hi, lo);
                size_t hb = (size_t)b * 1536 + j;
                g_h2[hb] = hi; g_h2[hb + 512] = hi; g_h2[hb + 1024] = lo;
                size_t ab = ((size_t)t * B_ + b) * 1536 + j;
                g_A2[ab] = hi; g_A2[ab + 512] = hi; g_A2[ab + 1024] = lo;
            }
        }
        grid_barrier();
    }
}

// ---------------- generic SGEMM (small shapes) ---------------------------
#define BM 64
#define BN 64
#define BK 16

__global__ __launch_bounds__(256) void sgemm2(
    const float* __restrict__ A, int lda,
    const float* __restrict__ W, int ldw,
    const float* __restrict__ bias,
    const float* __restrict__ D, int ldd,
    float* __restrict__ C, int ldc,
    int M, int N, int K)
{
    __shared__ float As[BK][BM + 1];
    __shared__ float Ws[BK][BN + 1];

    const int tid = threadIdx.x;
    const int tx = tid & 15;
    const int ty = tid >> 4;
    const int rowBase = blockIdx.y * BM;
    const int colBase = blockIdx.x * BN;

    float acc[4][4] = {};

    for (int k0 = 0; k0 < K; k0 += BK) {
        #pragma unroll
        for (int i = 0; i < 4; i++) {
            int lin = tid + i * 256;
            int r = lin >> 4;
            int c = lin & 15;
            int ar = rowBase + r;
            As[c][r] = (ar < M) ? A[(size_t)ar * lda + k0 + c] : 0.f;
            int wr = colBase + r;
            Ws[c][r] = (wr < N) ? W[(size_t)wr * ldw + k0 + c] : 0.f;
        }
        __syncthreads();
        #pragma unroll
        for (int kk = 0; kk < BK; kk++) {
            float a[4], w[4];
            #pragma unroll
            for (int i = 0; i < 4; i++) a[i] = As[kk][ty * 4 + i];
            #pragma unroll
            for (int j = 0; j < 4; j++) w[j] = Ws[kk][tx * 4 + j];
            #pragma unroll
            for (int i = 0; i < 4; i++)
                #pragma unroll
                for (int j = 0; j < 4; j++)
                    acc[i][j] += a[i] * w[j];
        }
        __syncthreads();
    }

    #pragma unroll
    for (int i = 0; i < 4; i++) {
        int r = rowBase + ty * 4 + i;
        if (r >= M) continue;
        #pragma unroll
        for (int j = 0; j < 4; j++) {
            int c = colBase + tx * 4 + j;
            if (c < N) {
                float v = acc[i][j];
                if (bias) v += bias[c];
                if (D)    v += D[(size_t)r * ldd + c];
                C[(size_t)r * ldc + c] = v;
            }
        }
    }
}

// ---------------- big SGEMM: BM=128, BN=64, 8x4 micro, double-buffered ---
#define GBM 128
#define GBN 64

__global__ __launch_bounds__(256) void sgemm_big(
    const float* __restrict__ A, int lda,
    const float* __restrict__ W, int ldw,
    const float* __restrict__ bias,
    float* __restrict__ C, int ldc,
    int M, int N, int K)
{
    __shared__ float As[2][16][GBM + 4];
    __shared__ float Ws[2][16][GBN + 4];

    const int tid = threadIdx.x;
    const int tx = tid & 15;
    const int ty = tid >> 4;
    const int rowBase = blockIdx.y * GBM;
    const int colBase = blockIdx.x * GBN;
    const int lc = tid & 15;

    float acc[8][4] = {};

    float a_pre[8], w_pre[4];
    #pragma unroll
    for (int i = 0; i < 8; i++) {
        int r = (tid + i * 256) >> 4;
        a_pre[i] = A[(size_t)(rowBase + r) * lda + lc];
    }
    #pragma unroll
    for (int i = 0; i < 4; i++) {
        int r = (tid + i * 256) >> 4;
        int wr = colBase + r;
        w_pre[i] = (wr < N) ? W[(size_t)wr * ldw + lc] : 0.f;
    }

    int buf = 0;
    for (int k0 = 0; k0 < K; k0 += 16) {
        #pragma unroll
        for (int i = 0; i < 8; i++) {
            int r = (tid + i * 256) >> 4;
            As[buf][lc][r] = a_pre[i];
        }
        #pragma unroll
        for (int i = 0; i < 4; i++) {
            int r = (tid + i * 256) >> 4;
            Ws[buf][lc][r] = w_pre[i];
        }
        __syncthreads();
        if (k0 + 16 < K) {
            #pragma unroll
            for (int i = 0; i < 8; i++) {
                int r = (tid + i * 256) >> 4;
                a_pre[i] = A[(size_t)(rowBase + r) * lda + k0 + 16 + lc];
            }
            #pragma unroll
            for (int i = 0; i < 4; i++) {
                int r = (tid + i * 256) >> 4;
                int wr = colBase + r;
                w_pre[i] = (wr < N) ? W[(size_t)wr * ldw + k0 + 16 + lc] : 0.f;
            }
        }
        #pragma unroll
        for (int kk = 0; kk < 16; kk++) {
            float a[8], w[4];
            #pragma unroll
            for (int j = 0; j < 4; j++) w[j] = Ws[buf][kk][tx * 4 + j];
            #pragma unroll
            for (int i = 0; i < 8; i++) a[i] = As[buf][kk][ty * 8 + i];
            #pragma unroll
            for (int i = 0; i < 8; i++)
                #pragma unroll
                for (int j = 0; j < 4; j++)
                    acc[i][j] += a[i] * w[j];
        }
        buf ^= 1;
    }

    #pragma unroll
    for (int i = 0; i < 8; i++) {
        int r = rowBase + ty * 8 + i;
        #pragma unroll
        for (int j = 0; j < 4; j++) {
            int c = colBase + tx * 4 + j;
            if (c < N) {
                float v = acc[i][j];
                if (bias) v += bias[c];
                C[(size_t)r * ldc + c] = v;
            }
        }
    }
}

// ---------------- BatchNorm1d (training mode) ----------------------------
__global__ void bn_kernel(const float* __restrict__ gamma, const float* __restrict__ beta)
{
    int e = blockIdx.x;
    int b = threadIdx.x;
    float v = g_f[b * E_ + e];
    __shared__ float red[B_];
    __shared__ float mu_s, var_s;

    red[b] = v;
    __syncthreads();
    for (int s = B_ / 2; s > 0; s >>= 1) {
        if (b < s) red[b] += red[b + s];
        __syncthreads();
    }
    if (b == 0) mu_s = red[0] * (1.0f / B_);
    __syncthreads();
    float d = v - mu_s;
    red[b] = d * d;
    __syncthreads();
    for (int s = B_ / 2; s > 0; s >>= 1) {
        if (b < s) red[b] += red[b + s];
        __syncthreads();
    }
    if (b == 0) var_s = red[0] * (1.0f / B_);
    __syncthreads();
    g_feats[b * E_ + e] = gamma[e] * d * rsqrtf(var_s + 1e-5f) + beta[e];
}

// ---------------- build X for all steps ----------------------------------
__global__ void build_X_kernel(const float* __restrict__ embed_W,
                               const int* __restrict__ captions)
{
    int idx = blockIdx.x * blockDim.x + threadIdx.x;
    int t = idx >> 16;
    int rem = idx & 65535;
    int b = rem >> 9;
    int e = rem & 511;
    float v;
    if (t == 0) v = g_feats[b * E_ + e];
    else        v = embed_W[(size_t)captions[b * T_ + (t - 1)] * E_ + e];
    g_X[idx] = v;
}

// ---------------- weight/state split builders ----------------------------
__global__ void init_h2_kernel()
{
    int idx = blockIdx.x * blockDim.x + threadIdx.x;    // 128*512
    int b = idx >> 9, k = idx & 511;
    __nv_bfloat16 hi, lo;
    split3(g_h[idx], hi, lo);
    size_t base = (size_t)b * 1536 + k;
    g_h2[base] = hi; g_h2[base + 512] = hi; g_h2[base + 1024] = lo;
}

__global__ void build_Whcat2_kernel(const float* __restrict__ attn_W,
                                    const float* __restrict__ gru_Whh)
{
    int idx = blockIdx.x * blockDim.x + threadIdx.x;    // 2048*512
    int n = idx >> 9, k = idx & 511;
    float w = (n < 512) ? attn_W[(size_t)n * 1024 + 512 + k]
                        : gru_Whh[(size_t)(n - 512) * 512 + k];
    __nv_bfloat16 hi, lo;
    split3(w, hi, lo);
    size_t base = (size_t)n * 1536 + k;
    g_Whcat2[base] = hi; g_Whcat2[base + 512] = lo; g_Whcat2[base + 1024] = hi;
}

__global__ void build_combWa2_kernel(const float* __restrict__ comb_W)
{
    int idx = blockIdx.x * blockDim.x + threadIdx.x;    // 512*512
    int n = idx >> 9, k = idx & 511;
    __nv_bfloat16 hi, lo;
    split3(comb_W[(size_t)n * 1024 + 512 + k], hi, lo);
    size_t base = (size_t)n * 1536 + k;
    g_combWa2[base] = hi; g_combWa2[base + 512] = lo; g_combWa2[base + 1024] = hi;
}

__global__ void build_Wih2_kernel(const float* __restrict__ gru_Wih)
{
    int idx = blockIdx.x * blockDim.x + threadIdx.x;    // 1536*512
    int n = idx >> 9, k = idx & 511;
    __nv_bfloat16 hi, lo;
    split3(gru_Wih[(size_t)n * 512 + k], hi, lo);
    size_t base = (size_t)n * 1536 + k;
    g_Wih2[base] = hi; g_Wih2[base + 512] = lo; g_Wih2[base + 1024] = hi;
}

__global__ void build_W2_kernel(const float* __restrict__ out_W)
{
    int idx = blockIdx.x * blockDim.x + threadIdx.x;    // 10000*512
    if (idx >= V_ * 512) return;
    int n = idx >> 9, k = idx & 511;
    __nv_bfloat16 hi, lo;
    split3(out_W[idx], hi, lo);
    size_t base = (size_t)n * 1536 + k;
    g_W2[base] = hi; g_W2[base + 512] = lo; g_W2[base + 1024] = hi;
}

// ---------------- log_softmax ---------------------------------------------
__global__ void logsoftmax_kernel(float* __restrict__ out)
{
    extern __shared__ float row[];
    __shared__ float red[256];
    __shared__ float mx_s, lse_s;
    int r = blockIdx.x;
    int tid = threadIdx.x;
    float* p = out + (size_t)r * V_;

    float mx = -3.4e38f;
    for (int i = tid; i < V_; i += 256) {
        float v = p[i];
        row[i] = v;
        mx = fmaxf(mx, v);
    }
    red[tid] = mx;
    __syncthreads();
    for (int s = 128; s > 0; s >>= 1) {
        if (tid < s) red[tid] = fmaxf(red[tid], red[tid + s]);
        __syncthreads();
    }
    if (tid == 0) mx_s = red[0];
    __syncthreads();

    float sum = 0.f;
    for (int i = tid; i < V_; i += 256) sum += expf(row[i] - mx_s);
    red[tid] = sum;
    __syncthreads();
    for (int s = 128; s > 0; s >>= 1) {
        if (tid < s) red[tid] += red[tid + s];
        __syncthreads();
    }
    if (tid == 0) lse_s = mx_s + logf(red[0]);
    __syncthreads();

    for (int i = tid; i < V_; i += 256) p[i] = row[i] - lse_s;
}

// ---------------- transpose hs [T,B,H] -> [B,T,H] ------------------------
__global__ void transpose_h_kernel(float* __restrict__ out2)
{
    int idx = blockIdx.x * blockDim.x + threadIdx.x;
    int j = idx & 511;
    int b = (idx >> 9) & 127;
    int t = idx >> 16;
    out2[((size_t)b * T_ + t) * H_ + j] = g_hs[idx];
}

// ---------------- host launch ---------------------------------------------
extern "C" void kernel_launch(void* const* d_in, const int* in_sizes, int n_in,
                              void* d_out, int out_size)
{
    const float* features = (const float*)d_in[0];
    const int*   captions = (const int*)d_in[1];
    const float* h0       = (const float*)d_in[2];
    const float* embed_W  = (const float*)d_in[4];
    const float* fc_W     = (const float*)d_in[5];
    const float* fc_b     = (const float*)d_in[6];
    const float* bn_gamma = (const float*)d_in[7];
    const float* bn_beta  = (const float*)d_in[8];
    const float* attn_W   = (const float*)d_in[9];
    const float* attn_b   = (const float*)d_in[10];
    const float* comb_W   = (const float*)d_in[11];
    const float* comb_b   = (const float*)d_in[12];
    const float* gru_Wih  = (const float*)d_in[13];
    const float* gru_Whh  = (const float*)d_in[14];
    const float* gru_bih  = (const float*)d_in[15];
    const float* gru_bhh  = (const float*)d_in[16];
    const float* out_W    = (const float*)d_in[17];
    const float* out_b    = (const float*)d_in[18];
    float* out = (float*)d_out;

    float *p_f, *p_h, *p_X, *p_AX, *p_CX;
    cudaGetSymbolAddress((void**)&p_f,  g_f);
    cudaGetSymbolAddress((void**)&p_h,  g_h);
    cudaGetSymbolAddress((void**)&p_X,  g_X);
    cudaGetSymbolAddress((void**)&p_AX, g_AX);
    cudaGetSymbolAddress((void**)&p_CX, g_CX);

    cudaMemcpyAsync(p_h, h0, (size_t)B_ * H_ * sizeof(float), cudaMemcpyDeviceToDevice);

    dim3 blk(256);

    // fc + batchnorm
    sgemm2<<<dim3(E_ / 64, B_ / 64), blk>>>(features, FIN_, fc_W, FIN_, fc_b,
                                            nullptr, 0, p_f, E_, B_, E_, FIN_);
    bn_kernel<<<E_, B_>>>(bn_gamma, bn_beta);

    // hoisted x-dependent work + weight splits
    build_X_kernel<<<(T_ * B_ * E_) / 256, 256>>>(embed_W, captions);
    init_h2_kernel<<<(B_ * 512) / 256, 256>>>();
    build_Whcat2_kernel<<<(2048 * 512) / 256, 256>>>(attn_W, gru_Whh);
    build_combWa2_kernel<<<(512 * 512) / 256, 256>>>(comb_W);
    build_Wih2_kernel<<<(1536 * 512) / 256, 256>>>(gru_Wih);
    build_W2_kernel<<<(V_ * 512 + 255) / 256, 256>>>(out_W);
    sgemm_big<<<dim3(H_ / GBN, (T_ * B_) / GBM), blk>>>(p_X, E_, attn_W, 1024, attn_b,
                                                        p_AX, H_, T_ * B_, H_, E_);
    sgemm_big<<<dim3(H_ / GBN, (T_ * B_) / GBM), blk>>>(p_X, E_, comb_W, 1024, comb_b,
                                                        p_CX, H_, T_ * B_, H_, E_);

    // fused persistent recurrence (HMMA GEMMs): ONE launch
    recurrence_kernel<<<NBLK, 256>>>(gru_bih, gru_bhh);

    // vocab projection on HMMA (A2 written by recurrence P5)
    vocab_mma_kernel<<<dim3((V_ + 127) / 128, (T_ * B_) / 128), blk>>>(out_b, out);
    logsoftmax_kernel<<<T_ * B_, 256, V_ * sizeof(float)>>>(out);

    transpose_h_kernel<<<(T_ * B_ * H_) / 256, 256>>>(out + (size_t)T_ * B_ * V_);
}

// round 17
// speedup vs baseline: 5.1654x; 1.4436x over previous
#include <cuda_runtime.h>
#include <cuda_bf16.h>
#include <math.h>
#include <stdint.h>

#define B_   128
#define T_   64
#define E_   512
#define H_   512
#define V_   10000
#define FIN_ 2048
#define NBLK 256

// ---------------- scratch (device globals; no allocation) ----------------
__device__ float g_f[B_ * E_];
__device__ float g_feats[B_ * E_];
__device__ float g_h[B_ * H_];
__device__ float g_X[T_ * B_ * E_];
__device__ float g_AX[T_ * B_ * H_];
__device__ float g_CX[T_ * B_ * H_];
__device__ float g_hproj[B_ * 2048];
__device__ float g_gx[B_ * 3 * H_];
__device__ float g_hs[T_ * B_ * H_];
__device__ float g_combWaT[512 * 512];           // combWa transposed (fp32)
__device__ float g_WfusedF[1536 * 512];          // Wih @ combWa (fp32)
__device__ float g_gxall[(size_t)T_ * B_ * 1536];// CX @ Wih^T + bih (all steps)

// bf16-split operands (K' = 3*512 = 1536)
__device__ __nv_bfloat16 g_A2[(size_t)T_ * B_ * 1536];     // vocab A (A-side)
__device__ __nv_bfloat16 g_W2[(size_t)V_ * 1536];          // vocab W (B-side)
__device__ __nv_bfloat16 g_Whcat2[2048 * 1536];            // B-side
__device__ __nv_bfloat16 g_Wih2[1536 * 1536];              // B-side
__device__ __nv_bfloat16 g_Wfused2[1536 * 1536];           // B-side
__device__ __nv_bfloat16 g_CX2[(size_t)T_ * B_ * 1536];    // A-side
__device__ __nv_bfloat16 g_h2[B_ * 1536];                  // A-side
__device__ __nv_bfloat16 g_applied2[B_ * 1536];            // A-side

// barrier state on separate 256B lines
__device__ __align__(256) unsigned int g_bar_count[64];
__device__ __align__(256) unsigned int g_bar_release[64];

// ---------------- software grid barrier (all NBLK blocks resident) -------
__device__ __forceinline__ void grid_barrier()
{
    __syncthreads();
    if (threadIdx.x == 0) {
        volatile unsigned int* rel = g_bar_release;
        unsigned int before = rel[0];
        __threadfence();
        unsigned int t = atomicAdd(&g_bar_count[0], 1u);
        if (t == NBLK - 1) {
            atomicExch(&g_bar_count[0], 0u);
            __threadfence();
            atomicAdd(&g_bar_release[0], 1u);
        } else {
            while (rel[0] == before) { }
        }
        __threadfence();
    }
    __syncthreads();
}

// ================= baseline-PTX tensor helpers (sm_80+) ==================
__device__ __forceinline__ uint32_t smem_u32(const void* p) {
    uint32_t a;
    asm("{ .reg .u64 t; cvta.to.shared.u64 t, %1; cvt.u32.u64 %0, t; }"
        : "=r"(a) : "l"(p));
    return a;
}
__device__ __forceinline__ void ldsm_x4(uint32_t* r, uint32_t addr) {
    asm volatile("ldmatrix.sync.aligned.m8n8.x4.shared.b16 {%0,%1,%2,%3}, [%4];"
                 : "=r"(r[0]), "=r"(r[1]), "=r"(r[2]), "=r"(r[3]) : "r"(addr));
}
__device__ __forceinline__ void ldsm_x2(uint32_t* r, uint32_t addr) {
    asm volatile("ldmatrix.sync.aligned.m8n8.x2.shared.b16 {%0,%1}, [%2];"
                 : "=r"(r[0]), "=r"(r[1]) : "r"(addr));
}
__device__ __forceinline__ void mma16816(float* c, const uint32_t* a, const uint32_t* b) {
    asm volatile(
        "mma.sync.aligned.m16n8k16.row.col.f32.bf16.bf16.f32 "
        "{%0,%1,%2,%3}, {%4,%5,%6,%7}, {%8,%9}, {%0,%1,%2,%3};"
        : "+f"(c[0]), "+f"(c[1]), "+f"(c[2]), "+f"(c[3])
        : "r"(a[0]), "r"(a[1]), "r"(a[2]), "r"(a[3]), "r"(b[0]), "r"(b[1]));
}

__device__ __forceinline__ void split3(float v, __nv_bfloat16& hi, __nv_bfloat16& lo) {
    hi = __float2bfloat16_rn(v);
    lo = __float2bfloat16_rn(v - __bfloat162float(hi));
}

// ---------------- generalized 128x128-tile mma GEMM ----------------------
// C[M,N] = A2[M,1536] @ W2[N,1536]^T + bias; M mult of 128 (grid.y), N guarded.
#define VSA 40
#define VBUF (128 * VSA)

__global__ __launch_bounds__(256) void mma128_kernel(
    const __nv_bfloat16* __restrict__ A2g, const __nv_bfloat16* __restrict__ W2,
    const float* __restrict__ bias, float* __restrict__ out, int N, int ldout)
{
    __shared__ __nv_bfloat16 sA[2][VBUF];
    __shared__ __nv_bfloat16 sB[2][VBUF];

    const int tid  = threadIdx.x;
    const int lane = tid & 31;
    const int wid  = tid >> 5;
    const int wm   = wid & 1;
    const int wn   = wid >> 1;
    const int tileN = blockIdx.x;
    const int tileM = blockIdx.y;

    const uint32_t sbA = smem_u32(sA);
    const uint32_t sbB = smem_u32(sB);

    const int rA = lane & 15;
    const int kA = (lane >> 4) * 8;
    const int rB = (lane & 7) + ((lane >> 4) << 3);
    const int kB = ((lane >> 3) & 1) * 8;

    const __nv_bfloat16* A2 = A2g + (size_t)(tileM * 128) * 1536;

    float acc[4][4][4];
    #pragma unroll
    for (int m = 0; m < 4; m++)
        #pragma unroll
        for (int n = 0; n < 4; n++)
            #pragma unroll
            for (int q = 0; q < 4; q++) acc[m][n][q] = 0.f;

    uint4 a_pre[2], b_pre[2];
    #pragma unroll
    for (int i = 0; i < 2; i++) {
        int lin = tid + i * 256;
        int row = lin >> 2, seg = lin & 3;
        a_pre[i] = *(const uint4*)(A2 + (size_t)row * 1536 + seg * 8);
        int n = tileN * 128 + row;
        b_pre[i] = (n < N) ? *(const uint4*)(W2 + (size_t)n * 1536 + seg * 8)
                           : make_uint4(0u, 0u, 0u, 0u);
    }

    int buf = 0;
    for (int k0 = 0; k0 < 1536; k0 += 32) {
        #pragma unroll
        for (int i = 0; i < 2; i++) {
            int lin = tid + i * 256;
            int row = lin >> 2, seg = lin & 3;
            *(uint4*)&sA[buf][row * VSA + seg * 8] = a_pre[i];
            *(uint4*)&sB[buf][row * VSA + seg * 8] = b_pre[i];
        }
        __syncthreads();
        if (k0 + 32 < 1536) {
            #pragma unroll
            for (int i = 0; i < 2; i++) {
                int lin = tid + i * 256;
                int row = lin >> 2, seg = lin & 3;
                a_pre[i] = *(const uint4*)(A2 + (size_t)row * 1536 + k0 + 32 + seg * 8);
                int n = tileN * 128 + row;
                b_pre[i] = (n < N) ? *(const uint4*)(W2 + (size_t)n * 1536 + k0 + 32 + seg * 8)
                                   : make_uint4(0u, 0u, 0u, 0u);
            }
        }
        #pragma unroll
        for (int kk = 0; kk < 32; kk += 16) {
            uint32_t afr[4][4], bfr[2][4];
            #pragma unroll
            for (int mt = 0; mt < 4; mt++) {
                uint32_t ad = sbA + (uint32_t)buf * (VBUF * 2)
                            + ((wm * 64 + mt * 16 + rA) * VSA + kk + kA) * 2;
                ldsm_x4(afr[mt], ad);
            }
            #pragma unroll
            for (int p = 0; p < 2; p++) {
                uint32_t bd = sbB + (uint32_t)buf * (VBUF * 2)
                            + ((wn * 32 + p * 16 + rB) * VSA + kk + kB) * 2;
                ldsm_x4(bfr[p], bd);
            }
            #pragma unroll
            for (int mt = 0; mt < 4; mt++)
                #pragma unroll
                for (int nt = 0; nt < 4; nt++)
                    mma16816(acc[mt][nt], afr[mt], &bfr[nt >> 1][(nt & 1) * 2]);
        }
        __syncthreads();
        buf ^= 1;
    }

    const int rbase = tileM * 128 + wm * 64;
    #pragma unroll
    for (int mt = 0; mt < 4; mt++) {
        int row = rbase + mt * 16 + (lane >> 2);
        #pragma unroll
        for (int nt = 0; nt < 4; nt++) {
            int col = tileN * 128 + wn * 32 + nt * 8 + (lane & 3) * 2;
            if (col < N) {
                float b0 = bias ? bias[col] : 0.f;
                float b1 = bias ? bias[col + 1] : 0.f;
                float2 v0 = make_float2(acc[mt][nt][0] + b0, acc[mt][nt][1] + b1);
                float2 v1 = make_float2(acc[mt][nt][2] + b0, acc[mt][nt][3] + b1);
                *(float2*)&out[(size_t)row * ldout + col] = v0;
                *(float2*)&out[(size_t)(row + 8) * ldout + col] = v1;
            }
        }
    }
}

// ---------------- 16x64 mma tile, k-chunk 64, for the recurrence ---------
// 256 thr, 8 warps, warp w -> n8 strip. K'=1536 in 24 chunks of 64.
__device__ __forceinline__ void mma_tile16x64_k64(
    const __nv_bfloat16* __restrict__ A2, int rowBase,
    const __nv_bfloat16* __restrict__ W2, int colBase,
    const float* __restrict__ Dres, int ldd,
    float* __restrict__ Cf, int ldcf,
    __nv_bfloat16 (&sA)[2][1152], __nv_bfloat16 (&sB)[2][4608])
{
    const int tid = threadIdx.x, lane = tid & 31, w = tid >> 5;
    const uint32_t baA = smem_u32(sA), baB = smem_u32(sB);
    const int rA = lane & 15, kA = (lane >> 4) * 8;
    const int rBl = lane & 7, kBl = ((lane >> 3) & 1) * 8;
    const int lrow = tid >> 3, lseg = tid & 7;     // load coords

    float acc[4] = {0.f, 0.f, 0.f, 0.f};

    uint4 bpre[2], apre;
    #pragma unroll
    for (int i = 0; i < 2; i++) {
        int s = tid + i * 256;
        int row = s >> 3, seg = s & 7;
        bpre[i] = *(const uint4*)(W2 + (size_t)(colBase + row) * 1536 + seg * 8);
    }
    if (tid < 128)
        apre = *(const uint4*)(A2 + (size_t)(rowBase + lrow) * 1536 + lseg * 8);

    int buf = 0;
    for (int k0 = 0; k0 < 1536; k0 += 64) {
        #pragma unroll
        for (int i = 0; i < 2; i++) {
            int s = tid + i * 256;
            int row = s >> 3, seg = s & 7;
            *(uint4*)&sB[buf][row * 72 + seg * 8] = bpre[i];
        }
        if (tid < 128)
            *(uint4*)&sA[buf][lrow * 72 + lseg * 8] = apre;
        __syncthreads();
        if (k0 + 64 < 1536) {
            #pragma unroll
            for (int i = 0; i < 2; i++) {
                int s = tid + i * 256;
                int row = s >> 3, seg = s & 7;
                bpre[i] = *(const uint4*)(W2 + (size_t)(colBase + row) * 1536 + k0 + 64 + seg * 8);
            }
            if (tid < 128)
                apre = *(const uint4*)(A2 + (size_t)(rowBase + lrow) * 1536 + k0 + 64 + lseg * 8);
        }
        uint32_t offA = baA + (uint32_t)buf * (1152 * 2);
        uint32_t offB = baB + (uint32_t)buf * (4608 * 2);
        #pragma unroll
        for (int kk = 0; kk < 64; kk += 16) {
            uint32_t afr[4], bfr[2];
            ldsm_x4(afr, offA + (uint32_t)((rA * 72 + kk + kA) * 2));
            ldsm_x2(bfr, offB + (uint32_t)(((w * 8 + rBl) * 72 + kk + kBl) * 2));
            mma16816(acc, afr, bfr);
        }
        buf ^= 1;
    }

    const int row0 = rowBase + (lane >> 2);
    const int colg = colBase + w * 8 + (lane & 3) * 2;
    float v00 = acc[0], v01 = acc[1], v10 = acc[2], v11 = acc[3];
    if (Dres) {
        v00 += Dres[(size_t)row0 * ldd + colg];
        v01 += Dres[(size_t)row0 * ldd + colg + 1];
        v10 += Dres[(size_t)(row0 + 8) * ldd + colg];
        v11 += Dres[(size_t)(row0 + 8) * ldd + colg + 1];
    }
    Cf[(size_t)row0 * ldcf + colg]           = v00;
    Cf[(size_t)row0 * ldcf + colg + 1]       = v01;
    Cf[(size_t)(row0 + 8) * ldcf + colg]     = v10;
    Cf[(size_t)(row0 + 8) * ldcf + colg + 1] = v11;
}

__device__ __forceinline__ float sigmoidf_(float x) { return 1.0f / (1.0f + expf(-x)); }

// ---------------- persistent recurrence kernel (4 phases/step) -----------
__global__ __launch_bounds__(256, 2) void recurrence_kernel(
    const float* __restrict__ bhh)
{
    __shared__ __nv_bfloat16 sA[2][1152];
    __shared__ __nv_bfloat16 sB[2][4608];
    __shared__ float red[256];
    const int bid = blockIdx.x;
    const int tid = threadIdx.x;

    for (int t = 0; t < T_; t++) {
        // P1: hproj[128,2048] = h2 @ Whcat2^T ; 8x32 = 256 tiles of 16x64
        {
            int tm = bid >> 5, tn = bid & 31;
            mma_tile16x64_k64(g_h2, tm * 16, g_Whcat2, tn * 64,
                              nullptr, 0, g_hproj, 2048, sA, sB);
        }
        grid_barrier();

        // P2: softmax(AX[t]+hproj[:, :512]) -> applied2 (triple)
        if (bid < B_) {
            const int b = bid;
            const float* ax = g_AX + ((size_t)t * B_ + b) * H_;
            const float* hp = g_hproj + (size_t)b * 2048;
            float v0 = ax[tid]       + hp[tid];
            float v1 = ax[tid + 256] + hp[tid + 256];
            red[tid] = fmaxf(v0, v1);
            __syncthreads();
            for (int s = 128; s > 0; s >>= 1) {
                if (tid < s) red[tid] = fmaxf(red[tid], red[tid + s]);
                __syncthreads();
            }
            float mx = red[0];
            __syncthreads();
            float e0 = expf(v0 - mx), e1 = expf(v1 - mx);
            red[tid] = e0 + e1;
            __syncthreads();
            for (int s = 128; s > 0; s >>= 1) {
                if (tid < s) red[tid] += red[tid + s];
                __syncthreads();
            }
            float inv = 1.0f / red[0];
            __syncthreads();
            float a0 = g_feats[b * E_ + tid]       * (e0 * inv);
            float a1 = g_feats[b * E_ + tid + 256] * (e1 * inv);
            __nv_bfloat16 hi, lo;
            split3(a0, hi, lo);
            g_applied2[(size_t)b * 1536 + tid] = hi;
            g_applied2[(size_t)b * 1536 + tid + 512] = hi;
            g_applied2[(size_t)b * 1536 + tid + 1024] = lo;
            split3(a1, hi, lo);
            g_applied2[(size_t)b * 1536 + tid + 256] = hi;
            g_applied2[(size_t)b * 1536 + tid + 768] = hi;
            g_applied2[(size_t)b * 1536 + tid + 1280] = lo;
        }
        grid_barrier();

        // P4': gx = gxall[t] + applied2 @ Wfused2^T ; 8x24 = 192 tiles
        if (bid < 192) {
            int tm = bid / 24, tn = bid % 24;
            mma_tile16x64_k64(g_applied2, tm * 16, g_Wfused2, tn * 64,
                              g_gxall + (size_t)t * B_ * 1536, 1536,
                              g_gx, 1536, sA, sB);
        }
        grid_barrier();

        // P5: GRU gates -> g_h (fp32), g_hs, g_h2 (triple), g_A2 row (triple)
        if (bid < B_) {
            const int b = bid;
            const float* gx = g_gx + (size_t)b * 1536;
            const float* hp = g_hproj + (size_t)b * 2048 + 512;
            #pragma unroll
            for (int u = 0; u < 2; u++) {
                int j = tid + u * 256;
                float r = sigmoidf_(gx[j]        + hp[j]        + bhh[j]);
                float z = sigmoidf_(gx[512 + j]  + hp[512 + j]  + bhh[512 + j]);
                float n = tanhf(gx[1024 + j] + r * (hp[1024 + j] + bhh[1024 + j]));
                float hprev = g_h[b * H_ + j];
                float h = (1.0f - z) * n + z * hprev;
                g_h[b * H_ + j] = h;
                g_hs[(size_t)t * B_ * H_ + b * H_ + j] = h;
                __nv_bfloat16 hi, lo;
                split3(h, hi, lo);
                size_t hb = (size_t)b * 1536 + j;
                g_h2[hb] = hi; g_h2[hb + 512] = hi; g_h2[hb + 1024] = lo;
                size_t ab = ((size_t)t * B_ + b) * 1536 + j;
                g_A2[ab] = hi; g_A2[ab + 512] = hi; g_A2[ab + 1024] = lo;
            }
        }
        grid_barrier();
    }
}

// ---------------- generic SGEMM (small shapes) ---------------------------
#define BM 64
#define BN 64
#define BK 16

__global__ __launch_bounds__(256) void sgemm2(
    const float* __restrict__ A, int lda,
    const float* __restrict__ W, int ldw,
    const float* __restrict__ bias,
    const float* __restrict__ D, int ldd,
    float* __restrict__ C, int ldc,
    int M, int N, int K)
{
    __shared__ float As[BK][BM + 1];
    __shared__ float Ws[BK][BN + 1];

    const int tid = threadIdx.x;
    const int tx = tid & 15;
    const int ty = tid >> 4;
    const int rowBase = blockIdx.y * BM;
    const int colBase = blockIdx.x * BN;

    float acc[4][4] = {};

    for (int k0 = 0; k0 < K; k0 += BK) {
        #pragma unroll
        for (int i = 0; i < 4; i++) {
            int lin = tid + i * 256;
            int r = lin >> 4;
            int c = lin & 15;
            int ar = rowBase + r;
            As[c][r] = (ar < M) ? A[(size_t)ar * lda + k0 + c] : 0.f;
            int wr = colBase + r;
            Ws[c][r] = (wr < N) ? W[(size_t)wr * ldw + k0 + c] : 0.f;
        }
        __syncthreads();
        #pragma unroll
        for (int kk = 0; kk < BK; kk++) {
            float a[4], w[4];
            #pragma unroll
            for (int i = 0; i < 4; i++) a[i] = As[kk][ty * 4 + i];
            #pragma unroll
            for (int j = 0; j < 4; j++) w[j] = Ws[kk][tx * 4 + j];
            #pragma unroll
            for (int i = 0; i < 4; i++)
                #pragma unroll
                for (int j = 0; j < 4; j++)
                    acc[i][j] += a[i] * w[j];
        }
        __syncthreads();
    }

    #pragma unroll
    for (int i = 0; i < 4; i++) {
        int r = rowBase + ty * 4 + i;
        if (r >= M) continue;
        #pragma unroll
        for (int j = 0; j < 4; j++) {
            int c = colBase + tx * 4 + j;
            if (c < N) {
                float v = acc[i][j];
                if (bias) v += bias[c];
                if (D)    v += D[(size_t)r * ldd + c];
                C[(size_t)r * ldc + c] = v;
            }
        }
    }
}

// ---------------- big SGEMM: BM=128, BN=64, 8x4 micro, double-buffered ---
#define GBM 128
#define GBN 64

__global__ __launch_bounds__(256) void sgemm_big(
    const float* __restrict__ A, int lda,
    const float* __restrict__ W, int ldw,
    const float* __restrict__ bias,
    float* __restrict__ C, int ldc,
    int M, int N, int K)
{
    __shared__ float As[2][16][GBM + 4];
    __shared__ float Ws[2][16][GBN + 4];

    const int tid = threadIdx.x;
    const int tx = tid & 15;
    const int ty = tid >> 4;
    const int rowBase = blockIdx.y * GBM;
    const int colBase = blockIdx.x * GBN;
    const int lc = tid & 15;

    float acc[8][4] = {};

    float a_pre[8], w_pre[4];
    #pragma unroll
    for (int i = 0; i < 8; i++) {
        int r = (tid + i * 256) >> 4;
        a_pre[i] = A[(size_t)(rowBase + r) * lda + lc];
    }
    #pragma unroll
    for (int i = 0; i < 4; i++) {
        int r = (tid + i * 256) >> 4;
        int wr = colBase + r;
        w_pre[i] = (wr < N) ? W[(size_t)wr * ldw + lc] : 0.f;
    }

    int buf = 0;
    for (int k0 = 0; k0 < K; k0 += 16) {
        #pragma unroll
        for (int i = 0; i < 8; i++) {
            int r = (tid + i * 256) >> 4;
            As[buf][lc][r] = a_pre[i];
        }
        #pragma unroll
        for (int i = 0; i < 4; i++) {
            int r = (tid + i * 256) >> 4;
            Ws[buf][lc][r] = w_pre[i];
        }
        __syncthreads();
        if (k0 + 16 < K) {
            #pragma unroll
            for (int i = 0; i < 8; i++) {
                int r = (tid + i * 256) >> 4;
                a_pre[i] = A[(size_t)(rowBase + r) * lda + k0 + 16 + lc];
            }
            #pragma unroll
            for (int i = 0; i < 4; i++) {
                int r = (tid + i * 256) >> 4;
                int wr = colBase + r;
                w_pre[i] = (wr < N) ? W[(size_t)wr * ldw + k0 + 16 + lc] : 0.f;
            }
        }
        #pragma unroll
        for (int kk = 0; kk < 16; kk++) {
            float a[8], w[4];
            #pragma unroll
            for (int j = 0; j < 4; j++) w[j] = Ws[buf][kk][tx * 4 + j];
            #pragma unroll
            for (int i = 0; i < 8; i++) a[i] = As[buf][kk][ty * 8 + i];
            #pragma unroll
            for (int i = 0; i < 8; i++)
                #pragma unroll
                for (int j = 0; j < 4; j++)
                    acc[i][j] += a[i] * w[j];
        }
        buf ^= 1;
    }

    #pragma unroll
    for (int i = 0; i < 8; i++) {
        int r = rowBase + ty * 8 + i;
        #pragma unroll
        for (int j = 0; j < 4; j++) {
            int c = colBase + tx * 4 + j;
            if (c < N) {
                float v = acc[i][j];
                if (bias) v += bias[c];
                C[(size_t)r * ldc + c] = v;
            }
        }
    }
}

// ---------------- BatchNorm1d (training mode) ----------------------------
__global__ void bn_kernel(const float* __restrict__ gamma, const float* __restrict__ beta)
{
    int e = blockIdx.x;
    int b = threadIdx.x;
    float v = g_f[b * E_ + e];
    __shared__ float red[B_];
    __shared__ float mu_s, var_s;

    red[b] = v;
    __syncthreads();
    for (int s = B_ / 2; s > 0; s >>= 1) {
        if (b < s) red[b] += red[b + s];
        __syncthreads();
    }
    if (b == 0) mu_s = red[0] * (1.0f / B_);
    __syncthreads();
    float d = v - mu_s;
    red[b] = d * d;
    __syncthreads();
    for (int s = B_ / 2; s > 0; s >>= 1) {
        if (b < s) red[b] += red[b + s];
        __syncthreads();
    }
    if (b == 0) var_s = red[0] * (1.0f / B_);
    __syncthreads();
    g_feats[b * E_ + e] = gamma[e] * d * rsqrtf(var_s + 1e-5f) + beta[e];
}

// ---------------- build X for all steps ----------------------------------
__global__ void build_X_kernel(const float* __restrict__ embed_W,
                               const int* __restrict__ captions)
{
    int idx = blockIdx.x * blockDim.x + threadIdx.x;
    int t = idx >> 16;
    int rem = idx & 65535;
    int b = rem >> 9;
    int e = rem & 511;
    float v;
    if (t == 0) v = g_feats[b * E_ + e];
    else        v = embed_W[(size_t)captions[b * T_ + (t - 1)] * E_ + e];
    g_X[idx] = v;
}

// ---------------- weight/state split builders ----------------------------
__global__ void init_h2_kernel()
{
    int idx = blockIdx.x * blockDim.x + threadIdx.x;    // 128*512
    int b = idx >> 9, k = idx & 511;
    __nv_bfloat16 hi, lo;
    split3(g_h[idx], hi, lo);
    size_t base = (size_t)b * 1536 + k;
    g_h2[base] = hi; g_h2[base + 512] = hi; g_h2[base + 1024] = lo;
}

__global__ void build_Whcat2_kernel(const float* __restrict__ attn_W,
                                    const float* __restrict__ gru_Whh)
{
    int idx = blockIdx.x * blockDim.x + threadIdx.x;    // 2048*512
    int n = idx >> 9, k = idx & 511;
    float w = (n < 512) ? attn_W[(size_t)n * 1024 + 512 + k]
                        : gru_Whh[(size_t)(n - 512) * 512 + k];
    __nv_bfloat16 hi, lo;
    split3(w, hi, lo);
    size_t base = (size_t)n * 1536 + k;
    g_Whcat2[base] = hi; g_Whcat2[base + 512] = lo; g_Whcat2[base + 1024] = hi;
}

__global__ void build_Wih2_kernel(const float* __restrict__ gru_Wih)
{
    int idx = blockIdx.x * blockDim.x + threadIdx.x;    // 1536*512
    int n = idx >> 9, k = idx & 511;
    __nv_bfloat16 hi, lo;
    split3(gru_Wih[(size_t)n * 512 + k], hi, lo);
    size_t base = (size_t)n * 1536 + k;
    g_Wih2[base] = hi; g_Wih2[base + 512] = lo; g_Wih2[base + 1024] = hi;
}

__global__ void build_W2_kernel(const float* __restrict__ out_W)
{
    int idx = blockIdx.x * blockDim.x + threadIdx.x;    // 10000*512
    if (idx >= V_ * 512) return;
    int n = idx >> 9, k = idx & 511;
    __nv_bfloat16 hi, lo;
    split3(out_W[idx], hi, lo);
    size_t base = (size_t)n * 1536 + k;
    g_W2[base] = hi; g_W2[base + 512] = lo; g_W2[base + 1024] = hi;
}

// combWaT[i,j] = comb_W[j*1024 + 512 + i]   (transpose of x-part slice)
__global__ void build_combWaT_kernel(const float* __restrict__ comb_W)
{
    int idx = blockIdx.x * blockDim.x + threadIdx.x;    // 512*512
    int i = idx >> 9, j = idx & 511;
    g_combWaT[i * 512 + j] = comb_W[(size_t)j * 1024 + 512 + i];
}

// split WfusedF -> Wfused2 (B-side: hi|lo|hi)
__global__ void build_Wfused2_kernel()
{
    int idx = blockIdx.x * blockDim.x + threadIdx.x;    // 1536*512
    int n = idx >> 9, k = idx & 511;
    __nv_bfloat16 hi, lo;
    split3(g_WfusedF[idx], hi, lo);
    size_t base = (size_t)n * 1536 + k;
    g_Wfused2[base] = hi; g_Wfused2[base + 512] = lo; g_Wfused2[base + 1024] = hi;
}

// split CX -> CX2 (A-side: hi|hi|lo)
__global__ void build_CX2_kernel()
{
    int idx = blockIdx.x * blockDim.x + threadIdx.x;    // 8192*512
    int r = idx >> 9, k = idx & 511;
    __nv_bfloat16 hi, lo;
    split3(g_CX[idx], hi, lo);
    size_t base = (size_t)r * 1536 + k;
    g_CX2[base] = hi; g_CX2[base + 512] = hi; g_CX2[base + 1024] = lo;
}

// ---------------- log_softmax ---------------------------------------------
__global__ void logsoftmax_kernel(float* __restrict__ out)
{
    extern __shared__ float row[];
    __shared__ float red[256];
    __shared__ float mx_s, lse_s;
    int r = blockIdx.x;
    int tid = threadIdx.x;
    float* p = out + (size_t)r * V_;

    float mx = -3.4e38f;
    for (int i = tid; i < V_; i += 256) {
        float v = p[i];
        row[i] = v;
        mx = fmaxf(mx, v);
    }
    red[tid] = mx;
    __syncthreads();
    for (int s = 128; s > 0; s >>= 1) {
        if (tid < s) red[tid] = fmaxf(red[tid], red[tid + s]);
        __syncthreads();
    }
    if (tid == 0) mx_s = red[0];
    __syncthreads();

    float sum = 0.f;
    for (int i = tid; i < V_; i += 256) sum += expf(row[i] - mx_s);
    red[tid] = sum;
    __syncthreads();
    for (int s = 128; s > 0; s >>= 1) {
        if (tid < s) red[tid] += red[tid + s];
        __syncthreads();
    }
    if (tid == 0) lse_s = mx_s + logf(red[0]);
    __syncthreads();

    for (int i = tid; i < V_; i += 256) p[i] = row[i] - lse_s;
}

// ---------------- transpose hs [T,B,H] -> [B,T,H] ------------------------
__global__ void transpose_h_kernel(float* __restrict__ out2)
{
    int idx = blockIdx.x * blockDim.x + threadIdx.x;
    int j = idx & 511;
    int b = (idx >> 9) & 127;
    int t = idx >> 16;
    out2[((size_t)b * T_ + t) * H_ + j] = g_hs[idx];
}

// ---------------- host launch ---------------------------------------------
extern "C" void kernel_launch(void* const* d_in, const int* in_sizes, int n_in,
                              void* d_out, int out_size)
{
    const float* features = (const float*)d_in[0];
    const int*   captions = (const int*)d_in[1];
    const float* h0       = (const float*)d_in[2];
    const float* embed_W  = (const float*)d_in[4];
    const float* fc_W     = (const float*)d_in[5];
    const float* fc_b     = (const float*)d_in[6];
    const float* bn_gamma = (const float*)d_in[7];
    const float* bn_beta  = (const float*)d_in[8];
    const float* attn_W   = (const float*)d_in[9];
    const float* attn_b   = (const float*)d_in[10];
    const float* comb_W   = (const float*)d_in[11];
    const float* comb_b   = (const float*)d_in[12];
    const float* gru_Wih  = (const float*)d_in[13];
    const float* gru_Whh  = (const float*)d_in[14];
    const float* gru_bih  = (const float*)d_in[15];
    const float* gru_bhh  = (const float*)d_in[16];
    const float* out_W    = (const float*)d_in[17];
    const float* out_b    = (const float*)d_in[18];
    float* out = (float*)d_out;

    float *p_f, *p_h, *p_X, *p_AX, *p_CX, *p_combWaT, *p_WfusedF, *p_gxall;
    __nv_bfloat16 *p_A2, *p_W2, *p_Wih2, *p_CX2;
    cudaGetSymbolAddress((void**)&p_f,       g_f);
    cudaGetSymbolAddress((void**)&p_h,       g_h);
    cudaGetSymbolAddress((void**)&p_X,       g_X);
    cudaGetSymbolAddress((void**)&p_AX,      g_AX);
    cudaGetSymbolAddress((void**)&p_CX,      g_CX);
    cudaGetSymbolAddress((void**)&p_combWaT, g_combWaT);
    cudaGetSymbolAddress((void**)&p_WfusedF, g_WfusedF);
    cudaGetSymbolAddress((void**)&p_gxall,   g_gxall);
    cudaGetSymbolAddress((void**)&p_A2,      g_A2);
    cudaGetSymbolAddress((void**)&p_W2,      g_W2);
    cudaGetSymbolAddress((void**)&p_Wih2,    g_Wih2);
    cudaGetSymbolAddress((void**)&p_CX2,     g_CX2);

    cudaMemcpyAsync(p_h, h0, (size_t)B_ * H_ * sizeof(float), cudaMemcpyDeviceToDevice);

    dim3 blk(256);

    // fc + batchnorm
    sgemm2<<<dim3(E_ / 64, B_ / 64), blk>>>(features, FIN_, fc_W, FIN_, fc_b,
                                            nullptr, 0, p_f, E_, B_, E_, FIN_);
    bn_kernel<<<E_, B_>>>(bn_gamma, bn_beta);

    // hoisted x-dependent work + weight splits
    build_X_kernel<<<(T_ * B_ * E_) / 256, 256>>>(embed_W, captions);
    init_h2_kernel<<<(B_ * 512) / 256, 256>>>();
    build_Whcat2_kernel<<<(2048 * 512) / 256, 256>>>(attn_W, gru_Whh);
    build_Wih2_kernel<<<(1536 * 512) / 256, 256>>>(gru_Wih);
    build_W2_kernel<<<(V_ * 512 + 255) / 256, 256>>>(out_W);
    // Wfused = Wih @ combWa   (fp32, exact)
    build_combWaT_kernel<<<(512 * 512) / 256, 256>>>(comb_W);
    sgemm2<<<dim3(512 / 64, 1536 / 64), blk>>>(gru_Wih, 512, p_combWaT, 512, nullptr,
                                               nullptr, 0, p_WfusedF, 512,
                                               1536, 512, 512);
    build_Wfused2_kernel<<<(1536 * 512) / 256, 256>>>();
    // AX, CX (fp32, exact)
    sgemm_big<<<dim3(H_ / GBN, (T_ * B_) / GBM), blk>>>(p_X, E_, attn_W, 1024, attn_b,
                                                        p_AX, H_, T_ * B_, H_, E_);
    sgemm_big<<<dim3(H_ / GBN, (T_ * B_) / GBM), blk>>>(p_X, E_, comb_W, 1024, comb_b,
                                                        p_CX, H_, T_ * B_, H_, E_);
    // gxall = CX @ Wih^T + bih  (HMMA, all 64 steps at once)
    build_CX2_kernel<<<(T_ * B_ * 512) / 256, 256>>>();
    mma128_kernel<<<dim3(1536 / 128, (T_ * B_) / 128), blk>>>(
        p_CX2, p_Wih2, gru_bih, p_gxall, 1536, 1536);

    // fused persistent recurrence (4 phases/step): ONE launch
    recurrence_kernel<<<NBLK, 256>>>(gru_bhh);

    // vocab projection on HMMA (A2 written by recurrence P5)
    mma128_kernel<<<dim3((V_ + 127) / 128, (T_ * B_) / 128), blk>>>(
        p_A2, p_W2, out_b, out, V_, V_);
    logsoftmax_kernel<<<T_ * B_, 256, V_ * sizeof(float)>>>(out);

    transpose_h_kernel<<<(T_ * B_ * H_) / 256, 256>>>(out + (size_t)T_ * B_ * V_);
}